// round 12
// baseline (speedup 1.0000x reference)
#include <cuda_runtime.h>
#include <cuda_bf16.h>
#include <cuda_fp16.h>
#include <math.h>
#include <stdint.h>

#define SEQ   2048
#define DIM   4096
#define NH    32
#define NKV   8
#define HD    128
#define KVD   1024
#define QKVD  6144          // DIM + 2*KVD (merged q|k|v output)
#define SCALE 0.08838834764831845f

// ---------------- scratch ----------------------------------------------------
__device__ float g_qkv[SEQ * QKVD];        // merged q|k|v projection output

__device__ __half g_xh[SEQ * DIM];
__device__ __half g_atth[SEQ * DIM];
__device__ __half g_wqkvT[QKVD * DIM];     // [wq^T ; wk^T ; wv^T] rows
__device__ __half g_woT[DIM * DIM];

// bf16 split Q/K/V for attention (Q pre-scaled, RoPE applied)
__device__ __nv_bfloat16 g_qs_hi[SEQ * DIM], g_qs_lo[SEQ * DIM];
__device__ __nv_bfloat16 g_ks_hi[SEQ * KVD], g_ks_lo[SEQ * KVD];
__device__ __nv_bfloat16 g_vs_hi[SEQ * KVD], g_vs_lo[SEQ * KVD];

// ---------------- PTX helpers (baseline PTX only) -----------------------------
__device__ __forceinline__ uint32_t smem_u32(const void* p) {
    uint32_t a;
    asm("{ .reg .u64 t; cvta.to.shared.u64 t, %1; cvt.u32.u64 %0, t; }"
        : "=r"(a) : "l"(p));
    return a;
}
#define CP_ASYNC16(dst, src) \
    asm volatile("cp.async.cg.shared.global [%0], [%1], 16;" :: "r"(dst), "l"(src) : "memory")
#define CP_COMMIT()  asm volatile("cp.async.commit_group;" ::: "memory")
#define CP_WAIT(n)   asm volatile("cp.async.wait_group %0;" :: "n"(n) : "memory")

#define LDSM_X4(r, addr)                                                      \
    asm volatile("ldmatrix.sync.aligned.m8n8.x4.shared.b16 {%0,%1,%2,%3}, [%4];" \
        : "=r"((r)[0]), "=r"((r)[1]), "=r"((r)[2]), "=r"((r)[3]) : "r"(addr))
#define LDSM_X4_T(r, addr)                                                    \
    asm volatile("ldmatrix.sync.aligned.m8n8.x4.trans.shared.b16 {%0,%1,%2,%3}, [%4];" \
        : "=r"((r)[0]), "=r"((r)[1]), "=r"((r)[2]), "=r"((r)[3]) : "r"(addr))

#define MMA_BF16(d, a, b0, b1)                                                \
    asm volatile("mma.sync.aligned.m16n8k16.row.col.f32.bf16.bf16.f32 "       \
        "{%0,%1,%2,%3}, {%4,%5,%6,%7}, {%8,%9}, {%0,%1,%2,%3};"               \
        : "+f"((d)[0]), "+f"((d)[1]), "+f"((d)[2]), "+f"((d)[3])              \
        : "r"((a)[0]), "r"((a)[1]), "r"((a)[2]), "r"((a)[3]), "r"(b0), "r"(b1))

#define MMA_F16(d, a, b0, b1)                                                 \
    asm volatile("mma.sync.aligned.m16n8k16.row.col.f32.f16.f16.f32 "         \
        "{%0,%1,%2,%3}, {%4,%5,%6,%7}, {%8,%9}, {%0,%1,%2,%3};"               \
        : "+f"((d)[0]), "+f"((d)[1]), "+f"((d)[2]), "+f"((d)[3])              \
        : "r"((a)[0]), "r"((a)[1]), "r"((a)[2]), "r"((a)[3]), "r"(b0), "r"(b1))

__device__ __forceinline__ uint32_t pack_bf16x2(float lo, float hi) {
    __nv_bfloat162 p = __float22bfloat162_rn(make_float2(lo, hi));
    return *(uint32_t*)&p;
}

// ---------------- fp32 -> fp16 convert (elementwise) ---------------------------
__global__ void hconv_kernel(const float* __restrict__ in,
                             __half* __restrict__ out, int n4)
{
    int i = blockIdx.x * blockDim.x + threadIdx.x;
    if (i >= n4) return;
    float4 v = ((const float4*)in)[i];
    __half2* op = (__half2*)out;
    op[i * 2]     = __floats2half2_rn(v.x, v.y);
    op[i * 2 + 1] = __floats2half2_rn(v.z, v.w);
}

// ---------------- transpose + convert: W[K,N] fp32 -> WT[N,K] fp16 -------------
__global__ void tconv_kernel(const float* __restrict__ B,
                             __half* __restrict__ T, int K, int N)
{
    __shared__ float tile[32][33];
    int n0 = blockIdx.x * 32, k0 = blockIdx.y * 32;
    int tx = threadIdx.x, ty = threadIdx.y;
#pragma unroll
    for (int i = 0; i < 32; i += 8)
        tile[ty + i][tx] = B[(size_t)(k0 + ty + i) * N + n0 + tx];
    __syncthreads();
#pragma unroll
    for (int i = 0; i < 32; i += 8)
        T[(size_t)(n0 + ty + i) * K + k0 + tx] = __float2half_rn(tile[tx][ty + i]);
}

// ---------------- fp16 mma.sync GEMM: C[M,N] = A[M,K] @ B[N,K]^T ---------------
// CTA tile 128x256, BK=32, 8 warps 2x4 -> warp tile 64x64 (4x8 mma tiles).
#define BK     32
#define ASTR   40                       // smem row stride (halves)
#define A_E    (128 * ASTR)             // A tile: 5120 halves
#define B_E    (256 * ASTR)             // B tile: 10240 halves
#define BUF_E  (A_E + B_E)
#define GEMM_SMEM (2 * BUF_E * 2)       // 61440 bytes

__global__ __launch_bounds__(256, 1) void gemm_h(
    const __half* __restrict__ A, const __half* __restrict__ B,
    float* __restrict__ C, int M, int N, int K)
{
    extern __shared__ __half smh[];
    const uint32_t sbase = smem_u32(smh);
    const int t = threadIdx.x, lane = t & 31, w = t >> 5;
    const int wm = w & 1, wn = w >> 1;           // 2 x 4 warp grid
    const int m0 = blockIdx.y << 7, n0 = blockIdx.x << 8;

    const __half* srcA = A + (size_t)m0 * K;
    const __half* srcB = B + (size_t)n0 * K;

    float acc[4][8][4];
#pragma unroll
    for (int a = 0; a < 4; a++)
#pragma unroll
        for (int b = 0; b < 8; b++)
#pragma unroll
            for (int c = 0; c < 4; c++) acc[a][b][c] = 0.f;

    const int lr = t >> 2, lc = (t & 3) * 8;     // load row / col chunk (halves)

    // prologue: buffer 0
    {
        uint32_t dA = sbase;
        uint32_t dB = sbase + A_E * 2;
        CP_ASYNC16(dA + (lr * ASTR + lc) * 2,        srcA + (size_t)lr * K + lc);
        CP_ASYNC16(dA + ((lr + 64) * ASTR + lc) * 2, srcA + (size_t)(lr + 64) * K + lc);
#pragma unroll
        for (int rr = 0; rr < 4; rr++)
            CP_ASYNC16(dB + ((lr + rr * 64) * ASTR + lc) * 2,
                       srcB + (size_t)(lr + rr * 64) * K + lc);
    }
    CP_COMMIT();

    const int niter = K / BK;
    for (int i = 0; i < niter; i++) {
        const int b = i & 1;
        if (i + 1 < niter) {
            const int nb = b ^ 1;
            const size_t koff = (size_t)(i + 1) * BK;
            uint32_t dA = sbase + (uint32_t)(nb * BUF_E) * 2;
            uint32_t dB = dA + A_E * 2;
            CP_ASYNC16(dA + (lr * ASTR + lc) * 2,        srcA + (size_t)lr * K + koff + lc);
            CP_ASYNC16(dA + ((lr + 64) * ASTR + lc) * 2, srcA + (size_t)(lr + 64) * K + koff + lc);
#pragma unroll
            for (int rr = 0; rr < 4; rr++)
                CP_ASYNC16(dB + ((lr + rr * 64) * ASTR + lc) * 2,
                           srcB + (size_t)(lr + rr * 64) * K + koff + lc);
            CP_COMMIT();
            CP_WAIT(1);
        } else {
            CP_WAIT(0);
        }
        __syncthreads();

        const uint32_t As = sbase + (uint32_t)(b * BUF_E) * 2;
        const uint32_t Bs = As + A_E * 2;

#pragma unroll
        for (int ks = 0; ks < 2; ks++) {
            const int koff = ks * 16 + (lane >> 4) * 8;
            const int arow = wm * 64 + (lane & 15);
            const int brow = wn * 64 + (lane & 15);

            uint32_t af[4][4], bf[4][4];
#pragma unroll
            for (int mt = 0; mt < 4; mt++)
                LDSM_X4(af[mt], As + (uint32_t)((arow + mt * 16) * ASTR + koff) * 2);
#pragma unroll
            for (int np = 0; np < 4; np++)
                LDSM_X4(bf[np], Bs + (uint32_t)((brow + np * 16) * ASTR + koff) * 2);
#pragma unroll
            for (int mt = 0; mt < 4; mt++)
#pragma unroll
                for (int nt = 0; nt < 8; nt++) {
                    const int np = nt >> 1, sel = nt & 1;
                    MMA_F16(acc[mt][nt], af[mt], bf[np][sel], bf[np][sel + 2]);
                }
        }
        __syncthreads();
    }

#pragma unroll
    for (int mt = 0; mt < 4; mt++) {
        const int r = m0 + wm * 64 + mt * 16 + (lane >> 2);
#pragma unroll
        for (int nt = 0; nt < 8; nt++) {
            const int c = n0 + wn * 64 + nt * 8 + (lane & 3) * 2;
            *(float2*)(C + (size_t)r * N + c) =
                make_float2(acc[mt][nt][0], acc[mt][nt][1]);
            *(float2*)(C + (size_t)(r + 8) * N + c) =
                make_float2(acc[mt][nt][2], acc[mt][nt][3]);
        }
    }
}

// ---------------- fused RoPE + scale + bf16 split (reads merged qkv) ----------
__global__ void rope_split_kernel(
    const float* __restrict__ qkv,
    const float* __restrict__ fc, const float* __restrict__ fs,
    __nv_bfloat16* __restrict__ qh, __nv_bfloat16* __restrict__ ql,
    __nv_bfloat16* __restrict__ kh, __nv_bfloat16* __restrict__ kl)
{
    int idx = blockIdx.x * blockDim.x + threadIdx.x;
    const int qn = SEQ * NH * (HD / 2);
    const int kn = SEQ * NKV * (HD / 2);
    float o1, o2;
    size_t off_out;
    __nv_bfloat16 *ph, *pl;
    if (idx < qn) {
        int s = idx / (NH * 64);
        int rem = idx - s * (NH * 64);
        int h = rem >> 6, i = rem & 63;
        float c = fc[s * 64 + i], sn = fs[s * 64 + i];
        size_t off_in = (size_t)s * QKVD + h * HD + 2 * i;
        float t1 = qkv[off_in], t2 = qkv[off_in + 1];
        o1 = (t1 * c - t2 * sn) * SCALE;
        o2 = (t1 * sn + t2 * c) * SCALE;
        off_out = (size_t)s * DIM + h * HD + 2 * i;
        ph = qh; pl = ql;
    } else if (idx < qn + kn) {
        int j = idx - qn;
        int s = j / (NKV * 64);
        int rem = j - s * (NKV * 64);
        int h = rem >> 6, i = rem & 63;
        float c = fc[s * 64 + i], sn = fs[s * 64 + i];
        size_t off_in = (size_t)s * QKVD + DIM + h * HD + 2 * i;
        float t1 = qkv[off_in], t2 = qkv[off_in + 1];
        o1 = t1 * c - t2 * sn;
        o2 = t1 * sn + t2 * c;
        off_out = (size_t)s * KVD + h * HD + 2 * i;
        ph = kh; pl = kl;
    } else return;
    __nv_bfloat16 h1 = __float2bfloat16(o1);
    __nv_bfloat16 h2 = __float2bfloat16(o2);
    __nv_bfloat162 hp; hp.x = h1; hp.y = h2;
    __nv_bfloat162 lp;
    lp.x = __float2bfloat16(o1 - __bfloat162float(h1));
    lp.y = __float2bfloat16(o2 - __bfloat162float(h2));
    *(__nv_bfloat162*)(ph + off_out) = hp;
    *(__nv_bfloat162*)(pl + off_out) = lp;
}

// ---------------- strided split fp32 -> bf16 hi/lo (V from merged qkv) --------
__global__ void vsplit_kernel(const float* __restrict__ qkv,
                              __nv_bfloat16* __restrict__ hi,
                              __nv_bfloat16* __restrict__ lo)
{
    int i = blockIdx.x * blockDim.x + threadIdx.x;   // over SEQ*KVD/4
    if (i >= SEQ * KVD / 4) return;
    int row = i / (KVD / 4), c4 = i - row * (KVD / 4);
    float4 v = *(const float4*)(qkv + (size_t)row * QKVD + DIM + KVD + c4 * 4);
    __nv_bfloat16 h0 = __float2bfloat16(v.x);
    __nv_bfloat16 h1 = __float2bfloat16(v.y);
    __nv_bfloat16 h2 = __float2bfloat16(v.z);
    __nv_bfloat16 h3 = __float2bfloat16(v.w);
    size_t o = (size_t)row * KVD + c4 * 4;
    __nv_bfloat162 a; a.x = h0; a.y = h1; *(__nv_bfloat162*)(hi + o) = a;
    __nv_bfloat162 b; b.x = h2; b.y = h3; *(__nv_bfloat162*)(hi + o + 2) = b;
    __nv_bfloat162 c;
    c.x = __float2bfloat16(v.x - __bfloat162float(h0));
    c.y = __float2bfloat16(v.y - __bfloat162float(h1));
    *(__nv_bfloat162*)(lo + o) = c;
    __nv_bfloat162 d;
    d.x = __float2bfloat16(v.z - __bfloat162float(h2));
    d.y = __float2bfloat16(v.w - __bfloat162float(h3));
    *(__nv_bfloat162*)(lo + o + 2) = d;
}

// ---------------- tensor-core flash attention (R5-proven; fp16 output) --------
#define AROWB 272
#define QT_B  (128 * AROWB)
#define KT_B  (64 * AROWB)
#define KVBUF (4 * KT_B)
#define ATT_SMEM (2 * QT_B + 2 * KVBUF)

__global__ __launch_bounds__(256) void attn_tc(
    const __nv_bfloat16* __restrict__ Qh, const __nv_bfloat16* __restrict__ Ql,
    const __nv_bfloat16* __restrict__ Kh, const __nv_bfloat16* __restrict__ Kl,
    const __nv_bfloat16* __restrict__ Vh, const __nv_bfloat16* __restrict__ Vl,
    __half* __restrict__ O)
{
    extern __shared__ char smc[];
    const uint32_t sb  = smem_u32(smc);
    const int t = threadIdx.x, lane = t & 31, w = t >> 5;
    const int h = blockIdx.y, q0 = blockIdx.x << 7, kvh = h >> 2;

    const uint32_t sQh = sb;
    const uint32_t sQl = sb + QT_B;
    const uint32_t sKV = sb + 2 * QT_B;

    {
        const __nv_bfloat16* qs[2] = { Qh, Ql };
        uint32_t qd[2] = { sQh, sQl };
#pragma unroll
        for (int tn = 0; tn < 2; tn++)
#pragma unroll
            for (int p = 0; p < 8; p++) {
                int chunk = t + p * 256;
                int row = chunk >> 4, c = chunk & 15;
                CP_ASYNC16(qd[tn] + row * AROWB + c * 16,
                           qs[tn] + (size_t)(q0 + row) * DIM + h * HD + c * 8);
            }
    }
    const __nv_bfloat16* kvsrc[4] = { Kh, Kl, Vh, Vl };
#pragma unroll
    for (int tn = 0; tn < 4; tn++)
#pragma unroll
        for (int p = 0; p < 4; p++) {
            int chunk = t + p * 256;
            int row = chunk >> 4, c = chunk & 15;
            CP_ASYNC16(sKV + tn * KT_B + row * AROWB + c * 16,
                       kvsrc[tn] + (size_t)row * KVD + kvh * HD + c * 8);
        }
    CP_COMMIT();

    float m0 = -INFINITY, m1 = -INFINITY, l0 = 0.f, l1 = 0.f;
    float oacc[16][4];
#pragma unroll
    for (int i = 0; i < 16; i++)
#pragma unroll
        for (int j = 0; j < 4; j++) oacc[i][j] = 0.f;

    const int NIT = SEQ / 64;
    for (int it = 0; it < NIT; it++) {
        CP_WAIT(0);
        __syncthreads();
        const uint32_t kvb = sKV + (it & 1) * KVBUF;
        if (it + 1 < NIT) {
            const uint32_t nb = sKV + ((it + 1) & 1) * KVBUF;
            const int k0n = (it + 1) * 64;
#pragma unroll
            for (int tn = 0; tn < 4; tn++)
#pragma unroll
                for (int p = 0; p < 4; p++) {
                    int chunk = t + p * 256;
                    int row = chunk >> 4, c = chunk & 15;
                    CP_ASYNC16(nb + tn * KT_B + row * AROWB + c * 16,
                               kvsrc[tn] + (size_t)(k0n + row) * KVD + kvh * HD + c * 8);
                }
            CP_COMMIT();
        }

        float sacc[8][4];
#pragma unroll
        for (int i = 0; i < 8; i++)
#pragma unroll
            for (int j = 0; j < 4; j++) sacc[i][j] = 0.f;

#pragma unroll
        for (int ks = 0; ks < 8; ks++) {
            const uint32_t aoff = (uint32_t)(16 * w + (lane & 15)) * AROWB
                                + ks * 32 + (lane >> 4) * 16;
            uint32_t ah[4], al[4];
            LDSM_X4(ah, sQh + aoff);
            LDSM_X4(al, sQl + aoff);
#pragma unroll
            for (int g = 0; g < 4; g++) {
                const uint32_t boff = (uint32_t)(g * 16 + (lane & 15)) * AROWB
                                    + ks * 32 + (lane >> 4) * 16;
                uint32_t bh[4], bl[4];
                LDSM_X4(bh, kvb + boff);
                LDSM_X4(bl, kvb + KT_B + boff);
#pragma unroll
                for (int sel = 0; sel < 2; sel++) {
                    MMA_BF16(sacc[2 * g + sel], ah, bh[sel], bh[sel + 2]);
                    MMA_BF16(sacc[2 * g + sel], ah, bl[sel], bl[sel + 2]);
                    MMA_BF16(sacc[2 * g + sel], al, bh[sel], bh[sel + 2]);
                }
            }
        }

        float mc0 = -INFINITY, mc1 = -INFINITY;
#pragma unroll
        for (int i = 0; i < 8; i++) {
            mc0 = fmaxf(mc0, fmaxf(sacc[i][0], sacc[i][1]));
            mc1 = fmaxf(mc1, fmaxf(sacc[i][2], sacc[i][3]));
        }
        mc0 = fmaxf(mc0, __shfl_xor_sync(0xffffffffu, mc0, 1));
        mc0 = fmaxf(mc0, __shfl_xor_sync(0xffffffffu, mc0, 2));
        mc1 = fmaxf(mc1, __shfl_xor_sync(0xffffffffu, mc1, 1));
        mc1 = fmaxf(mc1, __shfl_xor_sync(0xffffffffu, mc1, 2));
        const float mn0 = fmaxf(m0, mc0), mn1 = fmaxf(m1, mc1);
        const float alpha0 = __expf(m0 - mn0), alpha1 = __expf(m1 - mn1);
        m0 = mn0; m1 = mn1;
        float sum0 = 0.f, sum1 = 0.f;
#pragma unroll
        for (int i = 0; i < 8; i++) {
            sacc[i][0] = __expf(sacc[i][0] - mn0);
            sacc[i][1] = __expf(sacc[i][1] - mn0);
            sacc[i][2] = __expf(sacc[i][2] - mn1);
            sacc[i][3] = __expf(sacc[i][3] - mn1);
            sum0 += sacc[i][0] + sacc[i][1];
            sum1 += sacc[i][2] + sacc[i][3];
        }
        sum0 += __shfl_xor_sync(0xffffffffu, sum0, 1);
        sum0 += __shfl_xor_sync(0xffffffffu, sum0, 2);
        sum1 += __shfl_xor_sync(0xffffffffu, sum1, 1);
        sum1 += __shfl_xor_sync(0xffffffffu, sum1, 2);
        l0 = l0 * alpha0 + sum0;
        l1 = l1 * alpha1 + sum1;

#pragma unroll
        for (int i = 0; i < 16; i++) {
            oacc[i][0] *= alpha0; oacc[i][1] *= alpha0;
            oacc[i][2] *= alpha1; oacc[i][3] *= alpha1;
        }

        uint32_t pah[4][4], pal[4][4];
#pragma unroll
        for (int ks = 0; ks < 4; ks++) {
#pragma unroll
            for (int half = 0; half < 2; half++) {
                const int nt = 2 * ks + half;
                float e0 = sacc[nt][0], e1 = sacc[nt][1];
                float e2 = sacc[nt][2], e3 = sacc[nt][3];
                __nv_bfloat16 h0 = __float2bfloat16(e0);
                __nv_bfloat16 h1 = __float2bfloat16(e1);
                __nv_bfloat16 h2 = __float2bfloat16(e2);
                __nv_bfloat16 h3 = __float2bfloat16(e3);
                pah[ks][2 * half + 0] = pack_bf16x2(e0, e1);
                pah[ks][2 * half + 1] = pack_bf16x2(e2, e3);
                pal[ks][2 * half + 0] = pack_bf16x2(e0 - __bfloat162float(h0),
                                                    e1 - __bfloat162float(h1));
                pal[ks][2 * half + 1] = pack_bf16x2(e2 - __bfloat162float(h2),
                                                    e3 - __bfloat162float(h3));
            }
        }

#pragma unroll
        for (int ks = 0; ks < 4; ks++) {
#pragma unroll
            for (int g = 0; g < 8; g++) {
                const uint32_t voff = (uint32_t)(ks * 16 + (lane & 15)) * AROWB
                                    + (g * 16 + (lane >> 4) * 8) * 2;
                uint32_t vh[4], vl[4];
                LDSM_X4_T(vh, kvb + 2 * KT_B + voff);
                LDSM_X4_T(vl, kvb + 3 * KT_B + voff);
#pragma unroll
                for (int sel = 0; sel < 2; sel++) {
                    MMA_BF16(oacc[2 * g + sel], pah[ks], vh[2 * sel], vh[2 * sel + 1]);
                    MMA_BF16(oacc[2 * g + sel], pah[ks], vl[2 * sel], vl[2 * sel + 1]);
                    MMA_BF16(oacc[2 * g + sel], pal[ks], vh[2 * sel], vh[2 * sel + 1]);
                }
            }
        }
    }

    const float inv0 = 1.0f / l0, inv1 = 1.0f / l1;
    const int r0 = q0 + 16 * w + (lane >> 2);
    const int r1 = r0 + 8;
#pragma unroll
    for (int nt = 0; nt < 16; nt++) {
        const int col = h * HD + nt * 8 + (lane & 3) * 2;
        *(__half2*)(O + (size_t)r0 * DIM + col) =
            __floats2half2_rn(oacc[nt][0] * inv0, oacc[nt][1] * inv0);
        *(__half2*)(O + (size_t)r1 * DIM + col) =
            __floats2half2_rn(oacc[nt][2] * inv1, oacc[nt][3] * inv1);
    }
}

// ---------------- launch -------------------------------------------------------
extern "C" void kernel_launch(void* const* d_in, const int* in_sizes, int n_in,
                              void* d_out, int out_size)
{
    const float* x  = (const float*)d_in[0];
    const float* fc = (const float*)d_in[1];
    const float* fs = (const float*)d_in[2];
    const float* wq = (const float*)d_in[3];
    const float* wk = (const float*)d_in[4];
    const float* wv = (const float*)d_in[5];
    const float* wo = (const float*)d_in[6];
    float* out = (float*)d_out;

    float* qkv;
    cudaGetSymbolAddress((void**)&qkv, g_qkv);

    __half *xh, *atth, *wqkvT, *woT;
    cudaGetSymbolAddress((void**)&xh,    g_xh);
    cudaGetSymbolAddress((void**)&atth,  g_atth);
    cudaGetSymbolAddress((void**)&wqkvT, g_wqkvT);
    cudaGetSymbolAddress((void**)&woT,   g_woT);

    __nv_bfloat16 *qsh, *qsl, *ksh, *ksl, *vsh, *vsl;
    cudaGetSymbolAddress((void**)&qsh, g_qs_hi); cudaGetSymbolAddress((void**)&qsl, g_qs_lo);
    cudaGetSymbolAddress((void**)&ksh, g_ks_hi); cudaGetSymbolAddress((void**)&ksl, g_ks_lo);
    cudaGetSymbolAddress((void**)&vsh, g_vs_hi); cudaGetSymbolAddress((void**)&vsl, g_vs_lo);

    cudaFuncSetAttribute(gemm_h,
                         cudaFuncAttributeMaxDynamicSharedMemorySize, GEMM_SMEM);
    cudaFuncSetAttribute(attn_tc,
                         cudaFuncAttributeMaxDynamicSharedMemorySize, ATT_SMEM);

    // launches 1-4: convert x + q/k/v weights (wk/wv rows appended in wqkvT)
    hconv_kernel<<<(SEQ * DIM / 4 + 255) / 256, 256>>>(x, xh, SEQ * DIM / 4);
    tconv_kernel<<<dim3(DIM / 32, DIM / 32), dim3(32, 8)>>>(wq, wqkvT, DIM, DIM);
    tconv_kernel<<<dim3(KVD / 32, DIM / 32), dim3(32, 8)>>>(
        wk, wqkvT + (size_t)DIM * DIM, DIM, KVD);
    tconv_kernel<<<dim3(KVD / 32, DIM / 32), dim3(32, 8)>>>(
        wv, wqkvT + (size_t)(DIM + KVD) * DIM, DIM, KVD);

    // launch 5: merged QKV projection (profiled by ncu)
    gemm_h<<<dim3(QKVD / 256, SEQ / 128), 256, GEMM_SMEM>>>(
        xh, wqkvT, qkv, SEQ, QKVD, DIM);

    // remaining prep + attention + O-projection
    tconv_kernel<<<dim3(DIM / 32, DIM / 32), dim3(32, 8)>>>(wo, woT, DIM, DIM);

    int nrope = SEQ * (NH + NKV) * (HD / 2);
    rope_split_kernel<<<(nrope + 255) / 256, 256>>>(qkv, fc, fs, qsh, qsl, ksh, ksl);
    vsplit_kernel<<<(SEQ * KVD / 4 + 255) / 256, 256>>>(qkv, vsh, vsl);

    attn_tc<<<dim3(SEQ / 128, NH), 256, ATT_SMEM>>>(qsh, qsl, ksh, ksl, vsh, vsl, atth);

    gemm_h<<<dim3(DIM / 256, SEQ / 128), 256, GEMM_SMEM>>>(atth, woT, out, SEQ, DIM, DIM);
}

// round 13
// speedup vs baseline: 1.0003x; 1.0003x over previous
#include <cuda_runtime.h>
#include <cuda_bf16.h>
#include <cuda_fp16.h>
#include <math.h>
#include <stdint.h>

#define SEQ   2048
#define DIM   4096
#define NH    32
#define NKV   8
#define HD    128
#define KVD   1024
#define QKVD  6144          // DIM + 2*KVD (merged q|k|v output)
#define SCALE 0.08838834764831845f

// ---------------- scratch ----------------------------------------------------
__device__ float g_qkv[SEQ * QKVD];        // merged q|k|v projection output

__device__ __half g_xh[SEQ * DIM];
__device__ __half g_atth[SEQ * DIM];
__device__ __half g_wqkvT[QKVD * DIM];     // [wq^T ; wk^T ; wv^T] rows
__device__ __half g_woT[DIM * DIM];

// bf16 split Q/K/V for attention (Q pre-scaled, RoPE applied)
__device__ __nv_bfloat16 g_qs_hi[SEQ * DIM], g_qs_lo[SEQ * DIM];
__device__ __nv_bfloat16 g_ks_hi[SEQ * KVD], g_ks_lo[SEQ * KVD];
__device__ __nv_bfloat16 g_vs_hi[SEQ * KVD], g_vs_lo[SEQ * KVD];

// ---------------- PTX helpers (baseline PTX only) -----------------------------
__device__ __forceinline__ uint32_t smem_u32(const void* p) {
    uint32_t a;
    asm("{ .reg .u64 t; cvta.to.shared.u64 t, %1; cvt.u32.u64 %0, t; }"
        : "=r"(a) : "l"(p));
    return a;
}
#define CP_ASYNC16(dst, src) \
    asm volatile("cp.async.cg.shared.global [%0], [%1], 16;" :: "r"(dst), "l"(src) : "memory")
#define CP_COMMIT()  asm volatile("cp.async.commit_group;" ::: "memory")
#define CP_WAIT(n)   asm volatile("cp.async.wait_group %0;" :: "n"(n) : "memory")

#define LDSM_X4(r, addr)                                                      \
    asm volatile("ldmatrix.sync.aligned.m8n8.x4.shared.b16 {%0,%1,%2,%3}, [%4];" \
        : "=r"((r)[0]), "=r"((r)[1]), "=r"((r)[2]), "=r"((r)[3]) : "r"(addr))
#define LDSM_X4_T(r, addr)                                                    \
    asm volatile("ldmatrix.sync.aligned.m8n8.x4.trans.shared.b16 {%0,%1,%2,%3}, [%4];" \
        : "=r"((r)[0]), "=r"((r)[1]), "=r"((r)[2]), "=r"((r)[3]) : "r"(addr))

#define MMA_BF16(d, a, b0, b1)                                                \
    asm volatile("mma.sync.aligned.m16n8k16.row.col.f32.bf16.bf16.f32 "       \
        "{%0,%1,%2,%3}, {%4,%5,%6,%7}, {%8,%9}, {%0,%1,%2,%3};"               \
        : "+f"((d)[0]), "+f"((d)[1]), "+f"((d)[2]), "+f"((d)[3])              \
        : "r"((a)[0]), "r"((a)[1]), "r"((a)[2]), "r"((a)[3]), "r"(b0), "r"(b1))

#define MMA_F16(d, a, b0, b1)                                                 \
    asm volatile("mma.sync.aligned.m16n8k16.row.col.f32.f16.f16.f32 "         \
        "{%0,%1,%2,%3}, {%4,%5,%6,%7}, {%8,%9}, {%0,%1,%2,%3};"               \
        : "+f"((d)[0]), "+f"((d)[1]), "+f"((d)[2]), "+f"((d)[3])              \
        : "r"((a)[0]), "r"((a)[1]), "r"((a)[2]), "r"((a)[3]), "r"(b0), "r"(b1))

__device__ __forceinline__ uint32_t pack_bf16x2(float lo, float hi) {
    __nv_bfloat162 p = __float22bfloat162_rn(make_float2(lo, hi));
    return *(uint32_t*)&p;
}

// ---------------- fp32 -> fp16 convert (elementwise) ---------------------------
__global__ void hconv_kernel(const float* __restrict__ in,
                             __half* __restrict__ out, int n4)
{
    int i = blockIdx.x * blockDim.x + threadIdx.x;
    if (i >= n4) return;
    float4 v = ((const float4*)in)[i];
    __half2* op = (__half2*)out;
    op[i * 2]     = __floats2half2_rn(v.x, v.y);
    op[i * 2 + 1] = __floats2half2_rn(v.z, v.w);
}

// ---------------- transpose + convert: W[K,N] fp32 -> WT[N,K] fp16 -------------
__global__ void tconv_kernel(const float* __restrict__ B,
                             __half* __restrict__ T, int K, int N)
{
    __shared__ float tile[32][33];
    int n0 = blockIdx.x * 32, k0 = blockIdx.y * 32;
    int tx = threadIdx.x, ty = threadIdx.y;
#pragma unroll
    for (int i = 0; i < 32; i += 8)
        tile[ty + i][tx] = B[(size_t)(k0 + ty + i) * N + n0 + tx];
    __syncthreads();
#pragma unroll
    for (int i = 0; i < 32; i += 8)
        T[(size_t)(n0 + ty + i) * K + k0 + tx] = __float2half_rn(tile[tx][ty + i]);
}

// ---------------- fp16 mma.sync GEMM: C[M,N] = A[M,K] @ B[N,K]^T ---------------
// CTA tile 128x256, BK=32, 8 warps 2x4 -> warp tile 64x64 (4x8 mma tiles).
#define BK     32
#define ASTR   40                       // smem row stride (halves)
#define A_E    (128 * ASTR)             // A tile: 5120 halves
#define B_E    (256 * ASTR)             // B tile: 10240 halves
#define BUF_E  (A_E + B_E)
#define GEMM_SMEM (2 * BUF_E * 2)       // 61440 bytes

__global__ __launch_bounds__(256, 1) void gemm_h(
    const __half* __restrict__ A, const __half* __restrict__ B,
    float* __restrict__ C, int M, int N, int K)
{
    extern __shared__ __half smh[];
    const uint32_t sbase = smem_u32(smh);
    const int t = threadIdx.x, lane = t & 31, w = t >> 5;
    const int wm = w & 1, wn = w >> 1;           // 2 x 4 warp grid
    const int m0 = blockIdx.y << 7, n0 = blockIdx.x << 8;

    const __half* srcA = A + (size_t)m0 * K;
    const __half* srcB = B + (size_t)n0 * K;

    float acc[4][8][4];
#pragma unroll
    for (int a = 0; a < 4; a++)
#pragma unroll
        for (int b = 0; b < 8; b++)
#pragma unroll
            for (int c = 0; c < 4; c++) acc[a][b][c] = 0.f;

    const int lr = t >> 2, lc = (t & 3) * 8;     // load row / col chunk (halves)

    // prologue: buffer 0
    {
        uint32_t dA = sbase;
        uint32_t dB = sbase + A_E * 2;
        CP_ASYNC16(dA + (lr * ASTR + lc) * 2,        srcA + (size_t)lr * K + lc);
        CP_ASYNC16(dA + ((lr + 64) * ASTR + lc) * 2, srcA + (size_t)(lr + 64) * K + lc);
#pragma unroll
        for (int rr = 0; rr < 4; rr++)
            CP_ASYNC16(dB + ((lr + rr * 64) * ASTR + lc) * 2,
                       srcB + (size_t)(lr + rr * 64) * K + lc);
    }
    CP_COMMIT();

    const int niter = K / BK;
    for (int i = 0; i < niter; i++) {
        const int b = i & 1;
        if (i + 1 < niter) {
            const int nb = b ^ 1;
            const size_t koff = (size_t)(i + 1) * BK;
            uint32_t dA = sbase + (uint32_t)(nb * BUF_E) * 2;
            uint32_t dB = dA + A_E * 2;
            CP_ASYNC16(dA + (lr * ASTR + lc) * 2,        srcA + (size_t)lr * K + koff + lc);
            CP_ASYNC16(dA + ((lr + 64) * ASTR + lc) * 2, srcA + (size_t)(lr + 64) * K + koff + lc);
#pragma unroll
            for (int rr = 0; rr < 4; rr++)
                CP_ASYNC16(dB + ((lr + rr * 64) * ASTR + lc) * 2,
                           srcB + (size_t)(lr + rr * 64) * K + koff + lc);
            CP_COMMIT();
            CP_WAIT(1);
        } else {
            CP_WAIT(0);
        }
        __syncthreads();

        const uint32_t As = sbase + (uint32_t)(b * BUF_E) * 2;
        const uint32_t Bs = As + A_E * 2;

#pragma unroll
        for (int ks = 0; ks < 2; ks++) {
            const int koff = ks * 16 + (lane >> 4) * 8;
            const int arow = wm * 64 + (lane & 15);
            const int brow = wn * 64 + (lane & 15);

            uint32_t af[4][4], bf[4][4];
#pragma unroll
            for (int mt = 0; mt < 4; mt++)
                LDSM_X4(af[mt], As + (uint32_t)((arow + mt * 16) * ASTR + koff) * 2);
#pragma unroll
            for (int np = 0; np < 4; np++)
                LDSM_X4(bf[np], Bs + (uint32_t)((brow + np * 16) * ASTR + koff) * 2);
#pragma unroll
            for (int mt = 0; mt < 4; mt++)
#pragma unroll
                for (int nt = 0; nt < 8; nt++) {
                    const int np = nt >> 1, sel = nt & 1;
                    MMA_F16(acc[mt][nt], af[mt], bf[np][sel], bf[np][sel + 2]);
                }
        }
        __syncthreads();
    }

#pragma unroll
    for (int mt = 0; mt < 4; mt++) {
        const int r = m0 + wm * 64 + mt * 16 + (lane >> 2);
#pragma unroll
        for (int nt = 0; nt < 8; nt++) {
            const int c = n0 + wn * 64 + nt * 8 + (lane & 3) * 2;
            *(float2*)(C + (size_t)r * N + c) =
                make_float2(acc[mt][nt][0], acc[mt][nt][1]);
            *(float2*)(C + (size_t)(r + 8) * N + c) =
                make_float2(acc[mt][nt][2], acc[mt][nt][3]);
        }
    }
}

// ---------------- fused RoPE + scale + bf16 split (reads merged qkv) ----------
__global__ void rope_split_kernel(
    const float* __restrict__ qkv,
    const float* __restrict__ fc, const float* __restrict__ fs,
    __nv_bfloat16* __restrict__ qh, __nv_bfloat16* __restrict__ ql,
    __nv_bfloat16* __restrict__ kh, __nv_bfloat16* __restrict__ kl)
{
    int idx = blockIdx.x * blockDim.x + threadIdx.x;
    const int qn = SEQ * NH * (HD / 2);
    const int kn = SEQ * NKV * (HD / 2);
    float o1, o2;
    size_t off_out;
    __nv_bfloat16 *ph, *pl;
    if (idx < qn) {
        int s = idx / (NH * 64);
        int rem = idx - s * (NH * 64);
        int h = rem >> 6, i = rem & 63;
        float c = fc[s * 64 + i], sn = fs[s * 64 + i];
        size_t off_in = (size_t)s * QKVD + h * HD + 2 * i;
        float t1 = qkv[off_in], t2 = qkv[off_in + 1];
        o1 = (t1 * c - t2 * sn) * SCALE;
        o2 = (t1 * sn + t2 * c) * SCALE;
        off_out = (size_t)s * DIM + h * HD + 2 * i;
        ph = qh; pl = ql;
    } else if (idx < qn + kn) {
        int j = idx - qn;
        int s = j / (NKV * 64);
        int rem = j - s * (NKV * 64);
        int h = rem >> 6, i = rem & 63;
        float c = fc[s * 64 + i], sn = fs[s * 64 + i];
        size_t off_in = (size_t)s * QKVD + DIM + h * HD + 2 * i;
        float t1 = qkv[off_in], t2 = qkv[off_in + 1];
        o1 = t1 * c - t2 * sn;
        o2 = t1 * sn + t2 * c;
        off_out = (size_t)s * KVD + h * HD + 2 * i;
        ph = kh; pl = kl;
    } else return;
    __nv_bfloat16 h1 = __float2bfloat16(o1);
    __nv_bfloat16 h2 = __float2bfloat16(o2);
    __nv_bfloat162 hp; hp.x = h1; hp.y = h2;
    __nv_bfloat162 lp;
    lp.x = __float2bfloat16(o1 - __bfloat162float(h1));
    lp.y = __float2bfloat16(o2 - __bfloat162float(h2));
    *(__nv_bfloat162*)(ph + off_out) = hp;
    *(__nv_bfloat162*)(pl + off_out) = lp;
}

// ---------------- strided split fp32 -> bf16 hi/lo (V from merged qkv) --------
__global__ void vsplit_kernel(const float* __restrict__ qkv,
                              __nv_bfloat16* __restrict__ hi,
                              __nv_bfloat16* __restrict__ lo)
{
    int i = blockIdx.x * blockDim.x + threadIdx.x;   // over SEQ*KVD/4
    if (i >= SEQ * KVD / 4) return;
    int row = i / (KVD / 4), c4 = i - row * (KVD / 4);
    float4 v = *(const float4*)(qkv + (size_t)row * QKVD + DIM + KVD + c4 * 4);
    __nv_bfloat16 h0 = __float2bfloat16(v.x);
    __nv_bfloat16 h1 = __float2bfloat16(v.y);
    __nv_bfloat16 h2 = __float2bfloat16(v.z);
    __nv_bfloat16 h3 = __float2bfloat16(v.w);
    size_t o = (size_t)row * KVD + c4 * 4;
    __nv_bfloat162 a; a.x = h0; a.y = h1; *(__nv_bfloat162*)(hi + o) = a;
    __nv_bfloat162 b; b.x = h2; b.y = h3; *(__nv_bfloat162*)(hi + o + 2) = b;
    __nv_bfloat162 c;
    c.x = __float2bfloat16(v.x - __bfloat162float(h0));
    c.y = __float2bfloat16(v.y - __bfloat162float(h1));
    *(__nv_bfloat162*)(lo + o) = c;
    __nv_bfloat162 d;
    d.x = __float2bfloat16(v.z - __bfloat162float(h2));
    d.y = __float2bfloat16(v.w - __bfloat162float(h3));
    *(__nv_bfloat162*)(lo + o + 2) = d;
}

// ---------------- tensor-core flash attention (R5-proven; fp16 output) --------
#define AROWB 272
#define QT_B  (128 * AROWB)
#define KT_B  (64 * AROWB)
#define KVBUF (4 * KT_B)
#define ATT_SMEM (2 * QT_B + 2 * KVBUF)

__global__ __launch_bounds__(256) void attn_tc(
    const __nv_bfloat16* __restrict__ Qh, const __nv_bfloat16* __restrict__ Ql,
    const __nv_bfloat16* __restrict__ Kh, const __nv_bfloat16* __restrict__ Kl,
    const __nv_bfloat16* __restrict__ Vh, const __nv_bfloat16* __restrict__ Vl,
    __half* __restrict__ O)
{
    extern __shared__ char smc[];
    const uint32_t sb  = smem_u32(smc);
    const int t = threadIdx.x, lane = t & 31, w = t >> 5;
    const int h = blockIdx.y, q0 = blockIdx.x << 7, kvh = h >> 2;

    const uint32_t sQh = sb;
    const uint32_t sQl = sb + QT_B;
    const uint32_t sKV = sb + 2 * QT_B;

    {
        const __nv_bfloat16* qs[2] = { Qh, Ql };
        uint32_t qd[2] = { sQh, sQl };
#pragma unroll
        for (int tn = 0; tn < 2; tn++)
#pragma unroll
            for (int p = 0; p < 8; p++) {
                int chunk = t + p * 256;
                int row = chunk >> 4, c = chunk & 15;
                CP_ASYNC16(qd[tn] + row * AROWB + c * 16,
                           qs[tn] + (size_t)(q0 + row) * DIM + h * HD + c * 8);
            }
    }
    const __nv_bfloat16* kvsrc[4] = { Kh, Kl, Vh, Vl };
#pragma unroll
    for (int tn = 0; tn < 4; tn++)
#pragma unroll
        for (int p = 0; p < 4; p++) {
            int chunk = t + p * 256;
            int row = chunk >> 4, c = chunk & 15;
            CP_ASYNC16(sKV + tn * KT_B + row * AROWB + c * 16,
                       kvsrc[tn] + (size_t)row * KVD + kvh * HD + c * 8);
        }
    CP_COMMIT();

    float m0 = -INFINITY, m1 = -INFINITY, l0 = 0.f, l1 = 0.f;
    float oacc[16][4];
#pragma unroll
    for (int i = 0; i < 16; i++)
#pragma unroll
        for (int j = 0; j < 4; j++) oacc[i][j] = 0.f;

    const int NIT = SEQ / 64;
    for (int it = 0; it < NIT; it++) {
        CP_WAIT(0);
        __syncthreads();
        const uint32_t kvb = sKV + (it & 1) * KVBUF;
        if (it + 1 < NIT) {
            const uint32_t nb = sKV + ((it + 1) & 1) * KVBUF;
            const int k0n = (it + 1) * 64;
#pragma unroll
            for (int tn = 0; tn < 4; tn++)
#pragma unroll
                for (int p = 0; p < 4; p++) {
                    int chunk = t + p * 256;
                    int row = chunk >> 4, c = chunk & 15;
                    CP_ASYNC16(nb + tn * KT_B + row * AROWB + c * 16,
                               kvsrc[tn] + (size_t)(k0n + row) * KVD + kvh * HD + c * 8);
                }
            CP_COMMIT();
        }

        float sacc[8][4];
#pragma unroll
        for (int i = 0; i < 8; i++)
#pragma unroll
            for (int j = 0; j < 4; j++) sacc[i][j] = 0.f;

#pragma unroll
        for (int ks = 0; ks < 8; ks++) {
            const uint32_t aoff = (uint32_t)(16 * w + (lane & 15)) * AROWB
                                + ks * 32 + (lane >> 4) * 16;
            uint32_t ah[4], al[4];
            LDSM_X4(ah, sQh + aoff);
            LDSM_X4(al, sQl + aoff);
#pragma unroll
            for (int g = 0; g < 4; g++) {
                const uint32_t boff = (uint32_t)(g * 16 + (lane & 15)) * AROWB
                                    + ks * 32 + (lane >> 4) * 16;
                uint32_t bh[4], bl[4];
                LDSM_X4(bh, kvb + boff);
                LDSM_X4(bl, kvb + KT_B + boff);
#pragma unroll
                for (int sel = 0; sel < 2; sel++) {
                    MMA_BF16(sacc[2 * g + sel], ah, bh[sel], bh[sel + 2]);
                    MMA_BF16(sacc[2 * g + sel], ah, bl[sel], bl[sel + 2]);
                    MMA_BF16(sacc[2 * g + sel], al, bh[sel], bh[sel + 2]);
                }
            }
        }

        float mc0 = -INFINITY, mc1 = -INFINITY;
#pragma unroll
        for (int i = 0; i < 8; i++) {
            mc0 = fmaxf(mc0, fmaxf(sacc[i][0], sacc[i][1]));
            mc1 = fmaxf(mc1, fmaxf(sacc[i][2], sacc[i][3]));
        }
        mc0 = fmaxf(mc0, __shfl_xor_sync(0xffffffffu, mc0, 1));
        mc0 = fmaxf(mc0, __shfl_xor_sync(0xffffffffu, mc0, 2));
        mc1 = fmaxf(mc1, __shfl_xor_sync(0xffffffffu, mc1, 1));
        mc1 = fmaxf(mc1, __shfl_xor_sync(0xffffffffu, mc1, 2));
        const float mn0 = fmaxf(m0, mc0), mn1 = fmaxf(m1, mc1);
        const float alpha0 = __expf(m0 - mn0), alpha1 = __expf(m1 - mn1);
        m0 = mn0; m1 = mn1;
        float sum0 = 0.f, sum1 = 0.f;
#pragma unroll
        for (int i = 0; i < 8; i++) {
            sacc[i][0] = __expf(sacc[i][0] - mn0);
            sacc[i][1] = __expf(sacc[i][1] - mn0);
            sacc[i][2] = __expf(sacc[i][2] - mn1);
            sacc[i][3] = __expf(sacc[i][3] - mn1);
            sum0 += sacc[i][0] + sacc[i][1];
            sum1 += sacc[i][2] + sacc[i][3];
        }
        sum0 += __shfl_xor_sync(0xffffffffu, sum0, 1);
        sum0 += __shfl_xor_sync(0xffffffffu, sum0, 2);
        sum1 += __shfl_xor_sync(0xffffffffu, sum1, 1);
        sum1 += __shfl_xor_sync(0xffffffffu, sum1, 2);
        l0 = l0 * alpha0 + sum0;
        l1 = l1 * alpha1 + sum1;

#pragma unroll
        for (int i = 0; i < 16; i++) {
            oacc[i][0] *= alpha0; oacc[i][1] *= alpha0;
            oacc[i][2] *= alpha1; oacc[i][3] *= alpha1;
        }

        uint32_t pah[4][4], pal[4][4];
#pragma unroll
        for (int ks = 0; ks < 4; ks++) {
#pragma unroll
            for (int half = 0; half < 2; half++) {
                const int nt = 2 * ks + half;
                float e0 = sacc[nt][0], e1 = sacc[nt][1];
                float e2 = sacc[nt][2], e3 = sacc[nt][3];
                __nv_bfloat16 h0 = __float2bfloat16(e0);
                __nv_bfloat16 h1 = __float2bfloat16(e1);
                __nv_bfloat16 h2 = __float2bfloat16(e2);
                __nv_bfloat16 h3 = __float2bfloat16(e3);
                pah[ks][2 * half + 0] = pack_bf16x2(e0, e1);
                pah[ks][2 * half + 1] = pack_bf16x2(e2, e3);
                pal[ks][2 * half + 0] = pack_bf16x2(e0 - __bfloat162float(h0),
                                                    e1 - __bfloat162float(h1));
                pal[ks][2 * half + 1] = pack_bf16x2(e2 - __bfloat162float(h2),
                                                    e3 - __bfloat162float(h3));
            }
        }

#pragma unroll
        for (int ks = 0; ks < 4; ks++) {
#pragma unroll
            for (int g = 0; g < 8; g++) {
                const uint32_t voff = (uint32_t)(ks * 16 + (lane & 15)) * AROWB
                                    + (g * 16 + (lane >> 4) * 8) * 2;
                uint32_t vh[4], vl[4];
                LDSM_X4_T(vh, kvb + 2 * KT_B + voff);
                LDSM_X4_T(vl, kvb + 3 * KT_B + voff);
#pragma unroll
                for (int sel = 0; sel < 2; sel++) {
                    MMA_BF16(oacc[2 * g + sel], pah[ks], vh[2 * sel], vh[2 * sel + 1]);
                    MMA_BF16(oacc[2 * g + sel], pah[ks], vl[2 * sel], vl[2 * sel + 1]);
                    MMA_BF16(oacc[2 * g + sel], pal[ks], vh[2 * sel], vh[2 * sel + 1]);
                }
            }
        }
    }

    const float inv0 = 1.0f / l0, inv1 = 1.0f / l1;
    const int r0 = q0 + 16 * w + (lane >> 2);
    const int r1 = r0 + 8;
#pragma unroll
    for (int nt = 0; nt < 16; nt++) {
        const int col = h * HD + nt * 8 + (lane & 3) * 2;
        *(__half2*)(O + (size_t)r0 * DIM + col) =
            __floats2half2_rn(oacc[nt][0] * inv0, oacc[nt][1] * inv0);
        *(__half2*)(O + (size_t)r1 * DIM + col) =
            __floats2half2_rn(oacc[nt][2] * inv1, oacc[nt][3] * inv1);
    }
}

// ---------------- launch -------------------------------------------------------
extern "C" void kernel_launch(void* const* d_in, const int* in_sizes, int n_in,
                              void* d_out, int out_size)
{
    const float* x  = (const float*)d_in[0];
    const float* fc = (const float*)d_in[1];
    const float* fs = (const float*)d_in[2];
    const float* wq = (const float*)d_in[3];
    const float* wk = (const float*)d_in[4];
    const float* wv = (const float*)d_in[5];
    const float* wo = (const float*)d_in[6];
    float* out = (float*)d_out;

    float* qkv;
    cudaGetSymbolAddress((void**)&qkv, g_qkv);

    __half *xh, *atth, *wqkvT, *woT;
    cudaGetSymbolAddress((void**)&xh,    g_xh);
    cudaGetSymbolAddress((void**)&atth,  g_atth);
    cudaGetSymbolAddress((void**)&wqkvT, g_wqkvT);
    cudaGetSymbolAddress((void**)&woT,   g_woT);

    __nv_bfloat16 *qsh, *qsl, *ksh, *ksl, *vsh, *vsl;
    cudaGetSymbolAddress((void**)&qsh, g_qs_hi); cudaGetSymbolAddress((void**)&qsl, g_qs_lo);
    cudaGetSymbolAddress((void**)&ksh, g_ks_hi); cudaGetSymbolAddress((void**)&ksl, g_ks_lo);
    cudaGetSymbolAddress((void**)&vsh, g_vs_hi); cudaGetSymbolAddress((void**)&vsl, g_vs_lo);

    cudaFuncSetAttribute(gemm_h,
                         cudaFuncAttributeMaxDynamicSharedMemorySize, GEMM_SMEM);
    cudaFuncSetAttribute(attn_tc,
                         cudaFuncAttributeMaxDynamicSharedMemorySize, ATT_SMEM);

    // launches 1-4: convert x + q/k/v weights (wk/wv rows appended in wqkvT)
    hconv_kernel<<<(SEQ * DIM / 4 + 255) / 256, 256>>>(x, xh, SEQ * DIM / 4);
    tconv_kernel<<<dim3(DIM / 32, DIM / 32), dim3(32, 8)>>>(wq, wqkvT, DIM, DIM);
    tconv_kernel<<<dim3(KVD / 32, DIM / 32), dim3(32, 8)>>>(
        wk, wqkvT + (size_t)DIM * DIM, DIM, KVD);
    tconv_kernel<<<dim3(KVD / 32, DIM / 32), dim3(32, 8)>>>(
        wv, wqkvT + (size_t)(DIM + KVD) * DIM, DIM, KVD);

    // launch 5: merged QKV projection (profiled by ncu)
    gemm_h<<<dim3(QKVD / 256, SEQ / 128), 256, GEMM_SMEM>>>(
        xh, wqkvT, qkv, SEQ, QKVD, DIM);

    // remaining prep + attention + O-projection
    tconv_kernel<<<dim3(DIM / 32, DIM / 32), dim3(32, 8)>>>(wo, woT, DIM, DIM);

    int nrope = SEQ * (NH + NKV) * (HD / 2);
    rope_split_kernel<<<(nrope + 255) / 256, 256>>>(qkv, fc, fs, qsh, qsl, ksh, ksl);
    vsplit_kernel<<<(SEQ * KVD / 4 + 255) / 256, 256>>>(qkv, vsh, vsl);

    attn_tc<<<dim3(SEQ / 128, NH), 256, ATT_SMEM>>>(qsh, qsl, ksh, ksl, vsh, vsl, atth);

    gemm_h<<<dim3(DIM / 256, SEQ / 128), 256, GEMM_SMEM>>>(atth, woT, out, SEQ, DIM, DIM);
}

// round 14
// speedup vs baseline: 1.0008x; 1.0006x over previous
#include <cuda_runtime.h>
#include <cuda_bf16.h>
#include <cuda_fp16.h>
#include <math.h>
#include <stdint.h>

#define SEQ   2048
#define DIM   4096
#define NH    32
#define NKV   8
#define HD    128
#define KVD   1024
#define QKVD  6144          // DIM + 2*KVD (merged q|k|v output)
#define SCALE 0.08838834764831845f

// ---------------- scratch ----------------------------------------------------
__device__ float g_qkv[SEQ * QKVD];        // merged q|k|v projection output

__device__ __half g_xh[SEQ * DIM];
__device__ __half g_atth[SEQ * DIM];
__device__ __half g_wqkvT[QKVD * DIM];     // [wq^T ; wk^T ; wv^T] rows
__device__ __half g_woT[DIM * DIM];

// bf16 split Q/K/V for attention (Q pre-scaled, RoPE applied)
__device__ __nv_bfloat16 g_qs_hi[SEQ * DIM], g_qs_lo[SEQ * DIM];
__device__ __nv_bfloat16 g_ks_hi[SEQ * KVD], g_ks_lo[SEQ * KVD];
__device__ __nv_bfloat16 g_vs_hi[SEQ * KVD], g_vs_lo[SEQ * KVD];

// ---------------- PTX helpers (baseline PTX only) -----------------------------
__device__ __forceinline__ uint32_t smem_u32(const void* p) {
    uint32_t a;
    asm("{ .reg .u64 t; cvta.to.shared.u64 t, %1; cvt.u32.u64 %0, t; }"
        : "=r"(a) : "l"(p));
    return a;
}
#define CP_ASYNC16(dst, src) \
    asm volatile("cp.async.cg.shared.global [%0], [%1], 16;" :: "r"(dst), "l"(src) : "memory")
#define CP_COMMIT()  asm volatile("cp.async.commit_group;" ::: "memory")
#define CP_WAIT(n)   asm volatile("cp.async.wait_group %0;" :: "n"(n) : "memory")

#define LDSM_X4(r, addr)                                                      \
    asm volatile("ldmatrix.sync.aligned.m8n8.x4.shared.b16 {%0,%1,%2,%3}, [%4];" \
        : "=r"((r)[0]), "=r"((r)[1]), "=r"((r)[2]), "=r"((r)[3]) : "r"(addr))
#define LDSM_X4_T(r, addr)                                                    \
    asm volatile("ldmatrix.sync.aligned.m8n8.x4.trans.shared.b16 {%0,%1,%2,%3}, [%4];" \
        : "=r"((r)[0]), "=r"((r)[1]), "=r"((r)[2]), "=r"((r)[3]) : "r"(addr))

#define MMA_BF16(d, a, b0, b1)                                                \
    asm volatile("mma.sync.aligned.m16n8k16.row.col.f32.bf16.bf16.f32 "       \
        "{%0,%1,%2,%3}, {%4,%5,%6,%7}, {%8,%9}, {%0,%1,%2,%3};"               \
        : "+f"((d)[0]), "+f"((d)[1]), "+f"((d)[2]), "+f"((d)[3])              \
        : "r"((a)[0]), "r"((a)[1]), "r"((a)[2]), "r"((a)[3]), "r"(b0), "r"(b1))

#define MMA_F16(d, a, b0, b1)                                                 \
    asm volatile("mma.sync.aligned.m16n8k16.row.col.f32.f16.f16.f32 "         \
        "{%0,%1,%2,%3}, {%4,%5,%6,%7}, {%8,%9}, {%0,%1,%2,%3};"               \
        : "+f"((d)[0]), "+f"((d)[1]), "+f"((d)[2]), "+f"((d)[3])              \
        : "r"((a)[0]), "r"((a)[1]), "r"((a)[2]), "r"((a)[3]), "r"(b0), "r"(b1))

__device__ __forceinline__ uint32_t pack_bf16x2(float lo, float hi) {
    __nv_bfloat162 p = __float22bfloat162_rn(make_float2(lo, hi));
    return *(uint32_t*)&p;
}

// ---------------- fp32 -> fp16 convert (elementwise) ---------------------------
__global__ void hconv_kernel(const float* __restrict__ in,
                             __half* __restrict__ out, int n4)
{
    int i = blockIdx.x * blockDim.x + threadIdx.x;
    if (i >= n4) return;
    float4 v = ((const float4*)in)[i];
    __half2* op = (__half2*)out;
    op[i * 2]     = __floats2half2_rn(v.x, v.y);
    op[i * 2 + 1] = __floats2half2_rn(v.z, v.w);
}

// ---------------- transpose + convert: W[K,N] fp32 -> WT[N,K] fp16 -------------
__global__ void tconv_kernel(const float* __restrict__ B,
                             __half* __restrict__ T, int K, int N)
{
    __shared__ float tile[32][33];
    int n0 = blockIdx.x * 32, k0 = blockIdx.y * 32;
    int tx = threadIdx.x, ty = threadIdx.y;
#pragma unroll
    for (int i = 0; i < 32; i += 8)
        tile[ty + i][tx] = B[(size_t)(k0 + ty + i) * N + n0 + tx];
    __syncthreads();
#pragma unroll
    for (int i = 0; i < 32; i += 8)
        T[(size_t)(n0 + ty + i) * K + k0 + tx] = __float2half_rn(tile[tx][ty + i]);
}

// ---------------- fp16 mma.sync GEMM: C[M,N] = A[M,K] @ B[N,K]^T ---------------
// CTA tile 128x256, BK=32, 8 warps 2x4 -> warp tile 64x64 (4x8 mma tiles).
#define BK     32
#define ASTR   40                       // smem row stride (halves)
#define A_E    (128 * ASTR)             // A tile: 5120 halves
#define B_E    (256 * ASTR)             // B tile: 10240 halves
#define BUF_E  (A_E + B_E)
#define GEMM_SMEM (2 * BUF_E * 2)       // 61440 bytes

__global__ __launch_bounds__(256, 1) void gemm_h(
    const __half* __restrict__ A, const __half* __restrict__ B,
    float* __restrict__ C, int M, int N, int K)
{
    extern __shared__ __half smh[];
    const uint32_t sbase = smem_u32(smh);
    const int t = threadIdx.x, lane = t & 31, w = t >> 5;
    const int wm = w & 1, wn = w >> 1;           // 2 x 4 warp grid
    const int m0 = blockIdx.y << 7, n0 = blockIdx.x << 8;

    const __half* srcA = A + (size_t)m0 * K;
    const __half* srcB = B + (size_t)n0 * K;

    float acc[4][8][4];
#pragma unroll
    for (int a = 0; a < 4; a++)
#pragma unroll
        for (int b = 0; b < 8; b++)
#pragma unroll
            for (int c = 0; c < 4; c++) acc[a][b][c] = 0.f;

    const int lr = t >> 2, lc = (t & 3) * 8;     // load row / col chunk (halves)

    // prologue: buffer 0
    {
        uint32_t dA = sbase;
        uint32_t dB = sbase + A_E * 2;
        CP_ASYNC16(dA + (lr * ASTR + lc) * 2,        srcA + (size_t)lr * K + lc);
        CP_ASYNC16(dA + ((lr + 64) * ASTR + lc) * 2, srcA + (size_t)(lr + 64) * K + lc);
#pragma unroll
        for (int rr = 0; rr < 4; rr++)
            CP_ASYNC16(dB + ((lr + rr * 64) * ASTR + lc) * 2,
                       srcB + (size_t)(lr + rr * 64) * K + lc);
    }
    CP_COMMIT();

    const int niter = K / BK;
    for (int i = 0; i < niter; i++) {
        const int b = i & 1;
        if (i + 1 < niter) {
            const int nb = b ^ 1;
            const size_t koff = (size_t)(i + 1) * BK;
            uint32_t dA = sbase + (uint32_t)(nb * BUF_E) * 2;
            uint32_t dB = dA + A_E * 2;
            CP_ASYNC16(dA + (lr * ASTR + lc) * 2,        srcA + (size_t)lr * K + koff + lc);
            CP_ASYNC16(dA + ((lr + 64) * ASTR + lc) * 2, srcA + (size_t)(lr + 64) * K + koff + lc);
#pragma unroll
            for (int rr = 0; rr < 4; rr++)
                CP_ASYNC16(dB + ((lr + rr * 64) * ASTR + lc) * 2,
                           srcB + (size_t)(lr + rr * 64) * K + koff + lc);
            CP_COMMIT();
            CP_WAIT(1);
        } else {
            CP_WAIT(0);
        }
        __syncthreads();

        const uint32_t As = sbase + (uint32_t)(b * BUF_E) * 2;
        const uint32_t Bs = As + A_E * 2;

#pragma unroll
        for (int ks = 0; ks < 2; ks++) {
            const int koff = ks * 16 + (lane >> 4) * 8;
            const int arow = wm * 64 + (lane & 15);
            const int brow = wn * 64 + (lane & 15);

            uint32_t af[4][4], bf[4][4];
#pragma unroll
            for (int mt = 0; mt < 4; mt++)
                LDSM_X4(af[mt], As + (uint32_t)((arow + mt * 16) * ASTR + koff) * 2);
#pragma unroll
            for (int np = 0; np < 4; np++)
                LDSM_X4(bf[np], Bs + (uint32_t)((brow + np * 16) * ASTR + koff) * 2);
#pragma unroll
            for (int mt = 0; mt < 4; mt++)
#pragma unroll
                for (int nt = 0; nt < 8; nt++) {
                    const int np = nt >> 1, sel = nt & 1;
                    MMA_F16(acc[mt][nt], af[mt], bf[np][sel], bf[np][sel + 2]);
                }
        }
        __syncthreads();
    }

#pragma unroll
    for (int mt = 0; mt < 4; mt++) {
        const int r = m0 + wm * 64 + mt * 16 + (lane >> 2);
#pragma unroll
        for (int nt = 0; nt < 8; nt++) {
            const int c = n0 + wn * 64 + nt * 8 + (lane & 3) * 2;
            *(float2*)(C + (size_t)r * N + c) =
                make_float2(acc[mt][nt][0], acc[mt][nt][1]);
            *(float2*)(C + (size_t)(r + 8) * N + c) =
                make_float2(acc[mt][nt][2], acc[mt][nt][3]);
        }
    }
}

// ---------------- fused RoPE + scale + bf16 split (reads merged qkv) ----------
__global__ void rope_split_kernel(
    const float* __restrict__ qkv,
    const float* __restrict__ fc, const float* __restrict__ fs,
    __nv_bfloat16* __restrict__ qh, __nv_bfloat16* __restrict__ ql,
    __nv_bfloat16* __restrict__ kh, __nv_bfloat16* __restrict__ kl)
{
    int idx = blockIdx.x * blockDim.x + threadIdx.x;
    const int qn = SEQ * NH * (HD / 2);
    const int kn = SEQ * NKV * (HD / 2);
    float o1, o2;
    size_t off_out;
    __nv_bfloat16 *ph, *pl;
    if (idx < qn) {
        int s = idx / (NH * 64);
        int rem = idx - s * (NH * 64);
        int h = rem >> 6, i = rem & 63;
        float c = fc[s * 64 + i], sn = fs[s * 64 + i];
        size_t off_in = (size_t)s * QKVD + h * HD + 2 * i;
        float t1 = qkv[off_in], t2 = qkv[off_in + 1];
        o1 = (t1 * c - t2 * sn) * SCALE;
        o2 = (t1 * sn + t2 * c) * SCALE;
        off_out = (size_t)s * DIM + h * HD + 2 * i;
        ph = qh; pl = ql;
    } else if (idx < qn + kn) {
        int j = idx - qn;
        int s = j / (NKV * 64);
        int rem = j - s * (NKV * 64);
        int h = rem >> 6, i = rem & 63;
        float c = fc[s * 64 + i], sn = fs[s * 64 + i];
        size_t off_in = (size_t)s * QKVD + DIM + h * HD + 2 * i;
        float t1 = qkv[off_in], t2 = qkv[off_in + 1];
        o1 = t1 * c - t2 * sn;
        o2 = t1 * sn + t2 * c;
        off_out = (size_t)s * KVD + h * HD + 2 * i;
        ph = kh; pl = kl;
    } else return;
    __nv_bfloat16 h1 = __float2bfloat16(o1);
    __nv_bfloat16 h2 = __float2bfloat16(o2);
    __nv_bfloat162 hp; hp.x = h1; hp.y = h2;
    __nv_bfloat162 lp;
    lp.x = __float2bfloat16(o1 - __bfloat162float(h1));
    lp.y = __float2bfloat16(o2 - __bfloat162float(h2));
    *(__nv_bfloat162*)(ph + off_out) = hp;
    *(__nv_bfloat162*)(pl + off_out) = lp;
}

// ---------------- strided split fp32 -> bf16 hi/lo (V from merged qkv) --------
__global__ void vsplit_kernel(const float* __restrict__ qkv,
                              __nv_bfloat16* __restrict__ hi,
                              __nv_bfloat16* __restrict__ lo)
{
    int i = blockIdx.x * blockDim.x + threadIdx.x;   // over SEQ*KVD/4
    if (i >= SEQ * KVD / 4) return;
    int row = i / (KVD / 4), c4 = i - row * (KVD / 4);
    float4 v = *(const float4*)(qkv + (size_t)row * QKVD + DIM + KVD + c4 * 4);
    __nv_bfloat16 h0 = __float2bfloat16(v.x);
    __nv_bfloat16 h1 = __float2bfloat16(v.y);
    __nv_bfloat16 h2 = __float2bfloat16(v.z);
    __nv_bfloat16 h3 = __float2bfloat16(v.w);
    size_t o = (size_t)row * KVD + c4 * 4;
    __nv_bfloat162 a; a.x = h0; a.y = h1; *(__nv_bfloat162*)(hi + o) = a;
    __nv_bfloat162 b; b.x = h2; b.y = h3; *(__nv_bfloat162*)(hi + o + 2) = b;
    __nv_bfloat162 c;
    c.x = __float2bfloat16(v.x - __bfloat162float(h0));
    c.y = __float2bfloat16(v.y - __bfloat162float(h1));
    *(__nv_bfloat162*)(lo + o) = c;
    __nv_bfloat162 d;
    d.x = __float2bfloat16(v.z - __bfloat162float(h2));
    d.y = __float2bfloat16(v.w - __bfloat162float(h3));
    *(__nv_bfloat162*)(lo + o + 2) = d;
}

// ---------------- tensor-core flash attention (R5-proven; fp16 output) --------
#define AROWB 272
#define QT_B  (128 * AROWB)
#define KT_B  (64 * AROWB)
#define KVBUF (4 * KT_B)
#define ATT_SMEM (2 * QT_B + 2 * KVBUF)

__global__ __launch_bounds__(256) void attn_tc(
    const __nv_bfloat16* __restrict__ Qh, const __nv_bfloat16* __restrict__ Ql,
    const __nv_bfloat16* __restrict__ Kh, const __nv_bfloat16* __restrict__ Kl,
    const __nv_bfloat16* __restrict__ Vh, const __nv_bfloat16* __restrict__ Vl,
    __half* __restrict__ O)
{
    extern __shared__ char smc[];
    const uint32_t sb  = smem_u32(smc);
    const int t = threadIdx.x, lane = t & 31, w = t >> 5;
    const int h = blockIdx.y, q0 = blockIdx.x << 7, kvh = h >> 2;

    const uint32_t sQh = sb;
    const uint32_t sQl = sb + QT_B;
    const uint32_t sKV = sb + 2 * QT_B;

    {
        const __nv_bfloat16* qs[2] = { Qh, Ql };
        uint32_t qd[2] = { sQh, sQl };
#pragma unroll
        for (int tn = 0; tn < 2; tn++)
#pragma unroll
            for (int p = 0; p < 8; p++) {
                int chunk = t + p * 256;
                int row = chunk >> 4, c = chunk & 15;
                CP_ASYNC16(qd[tn] + row * AROWB + c * 16,
                           qs[tn] + (size_t)(q0 + row) * DIM + h * HD + c * 8);
            }
    }
    const __nv_bfloat16* kvsrc[4] = { Kh, Kl, Vh, Vl };
#pragma unroll
    for (int tn = 0; tn < 4; tn++)
#pragma unroll
        for (int p = 0; p < 4; p++) {
            int chunk = t + p * 256;
            int row = chunk >> 4, c = chunk & 15;
            CP_ASYNC16(sKV + tn * KT_B + row * AROWB + c * 16,
                       kvsrc[tn] + (size_t)row * KVD + kvh * HD + c * 8);
        }
    CP_COMMIT();

    float m0 = -INFINITY, m1 = -INFINITY, l0 = 0.f, l1 = 0.f;
    float oacc[16][4];
#pragma unroll
    for (int i = 0; i < 16; i++)
#pragma unroll
        for (int j = 0; j < 4; j++) oacc[i][j] = 0.f;

    const int NIT = SEQ / 64;
    for (int it = 0; it < NIT; it++) {
        CP_WAIT(0);
        __syncthreads();
        const uint32_t kvb = sKV + (it & 1) * KVBUF;
        if (it + 1 < NIT) {
            const uint32_t nb = sKV + ((it + 1) & 1) * KVBUF;
            const int k0n = (it + 1) * 64;
#pragma unroll
            for (int tn = 0; tn < 4; tn++)
#pragma unroll
                for (int p = 0; p < 4; p++) {
                    int chunk = t + p * 256;
                    int row = chunk >> 4, c = chunk & 15;
                    CP_ASYNC16(nb + tn * KT_B + row * AROWB + c * 16,
                               kvsrc[tn] + (size_t)(k0n + row) * KVD + kvh * HD + c * 8);
                }
            CP_COMMIT();
        }

        float sacc[8][4];
#pragma unroll
        for (int i = 0; i < 8; i++)
#pragma unroll
            for (int j = 0; j < 4; j++) sacc[i][j] = 0.f;

#pragma unroll
        for (int ks = 0; ks < 8; ks++) {
            const uint32_t aoff = (uint32_t)(16 * w + (lane & 15)) * AROWB
                                + ks * 32 + (lane >> 4) * 16;
            uint32_t ah[4], al[4];
            LDSM_X4(ah, sQh + aoff);
            LDSM_X4(al, sQl + aoff);
#pragma unroll
            for (int g = 0; g < 4; g++) {
                const uint32_t boff = (uint32_t)(g * 16 + (lane & 15)) * AROWB
                                    + ks * 32 + (lane >> 4) * 16;
                uint32_t bh[4], bl[4];
                LDSM_X4(bh, kvb + boff);
                LDSM_X4(bl, kvb + KT_B + boff);
#pragma unroll
                for (int sel = 0; sel < 2; sel++) {
                    MMA_BF16(sacc[2 * g + sel], ah, bh[sel], bh[sel + 2]);
                    MMA_BF16(sacc[2 * g + sel], ah, bl[sel], bl[sel + 2]);
                    MMA_BF16(sacc[2 * g + sel], al, bh[sel], bh[sel + 2]);
                }
            }
        }

        float mc0 = -INFINITY, mc1 = -INFINITY;
#pragma unroll
        for (int i = 0; i < 8; i++) {
            mc0 = fmaxf(mc0, fmaxf(sacc[i][0], sacc[i][1]));
            mc1 = fmaxf(mc1, fmaxf(sacc[i][2], sacc[i][3]));
        }
        mc0 = fmaxf(mc0, __shfl_xor_sync(0xffffffffu, mc0, 1));
        mc0 = fmaxf(mc0, __shfl_xor_sync(0xffffffffu, mc0, 2));
        mc1 = fmaxf(mc1, __shfl_xor_sync(0xffffffffu, mc1, 1));
        mc1 = fmaxf(mc1, __shfl_xor_sync(0xffffffffu, mc1, 2));
        const float mn0 = fmaxf(m0, mc0), mn1 = fmaxf(m1, mc1);
        const float alpha0 = __expf(m0 - mn0), alpha1 = __expf(m1 - mn1);
        m0 = mn0; m1 = mn1;
        float sum0 = 0.f, sum1 = 0.f;
#pragma unroll
        for (int i = 0; i < 8; i++) {
            sacc[i][0] = __expf(sacc[i][0] - mn0);
            sacc[i][1] = __expf(sacc[i][1] - mn0);
            sacc[i][2] = __expf(sacc[i][2] - mn1);
            sacc[i][3] = __expf(sacc[i][3] - mn1);
            sum0 += sacc[i][0] + sacc[i][1];
            sum1 += sacc[i][2] + sacc[i][3];
        }
        sum0 += __shfl_xor_sync(0xffffffffu, sum0, 1);
        sum0 += __shfl_xor_sync(0xffffffffu, sum0, 2);
        sum1 += __shfl_xor_sync(0xffffffffu, sum1, 1);
        sum1 += __shfl_xor_sync(0xffffffffu, sum1, 2);
        l0 = l0 * alpha0 + sum0;
        l1 = l1 * alpha1 + sum1;

#pragma unroll
        for (int i = 0; i < 16; i++) {
            oacc[i][0] *= alpha0; oacc[i][1] *= alpha0;
            oacc[i][2] *= alpha1; oacc[i][3] *= alpha1;
        }

        uint32_t pah[4][4], pal[4][4];
#pragma unroll
        for (int ks = 0; ks < 4; ks++) {
#pragma unroll
            for (int half = 0; half < 2; half++) {
                const int nt = 2 * ks + half;
                float e0 = sacc[nt][0], e1 = sacc[nt][1];
                float e2 = sacc[nt][2], e3 = sacc[nt][3];
                __nv_bfloat16 h0 = __float2bfloat16(e0);
                __nv_bfloat16 h1 = __float2bfloat16(e1);
                __nv_bfloat16 h2 = __float2bfloat16(e2);
                __nv_bfloat16 h3 = __float2bfloat16(e3);
                pah[ks][2 * half + 0] = pack_bf16x2(e0, e1);
                pah[ks][2 * half + 1] = pack_bf16x2(e2, e3);
                pal[ks][2 * half + 0] = pack_bf16x2(e0 - __bfloat162float(h0),
                                                    e1 - __bfloat162float(h1));
                pal[ks][2 * half + 1] = pack_bf16x2(e2 - __bfloat162float(h2),
                                                    e3 - __bfloat162float(h3));
            }
        }

#pragma unroll
        for (int ks = 0; ks < 4; ks++) {
#pragma unroll
            for (int g = 0; g < 8; g++) {
                const uint32_t voff = (uint32_t)(ks * 16 + (lane & 15)) * AROWB
                                    + (g * 16 + (lane >> 4) * 8) * 2;
                uint32_t vh[4], vl[4];
                LDSM_X4_T(vh, kvb + 2 * KT_B + voff);
                LDSM_X4_T(vl, kvb + 3 * KT_B + voff);
#pragma unroll
                for (int sel = 0; sel < 2; sel++) {
                    MMA_BF16(oacc[2 * g + sel], pah[ks], vh[2 * sel], vh[2 * sel + 1]);
                    MMA_BF16(oacc[2 * g + sel], pah[ks], vl[2 * sel], vl[2 * sel + 1]);
                    MMA_BF16(oacc[2 * g + sel], pal[ks], vh[2 * sel], vh[2 * sel + 1]);
                }
            }
        }
    }

    const float inv0 = 1.0f / l0, inv1 = 1.0f / l1;
    const int r0 = q0 + 16 * w + (lane >> 2);
    const int r1 = r0 + 8;
#pragma unroll
    for (int nt = 0; nt < 16; nt++) {
        const int col = h * HD + nt * 8 + (lane & 3) * 2;
        *(__half2*)(O + (size_t)r0 * DIM + col) =
            __floats2half2_rn(oacc[nt][0] * inv0, oacc[nt][1] * inv0);
        *(__half2*)(O + (size_t)r1 * DIM + col) =
            __floats2half2_rn(oacc[nt][2] * inv1, oacc[nt][3] * inv1);
    }
}

// ---------------- launch -------------------------------------------------------
extern "C" void kernel_launch(void* const* d_in, const int* in_sizes, int n_in,
                              void* d_out, int out_size)
{
    const float* x  = (const float*)d_in[0];
    const float* fc = (const float*)d_in[1];
    const float* fs = (const float*)d_in[2];
    const float* wq = (const float*)d_in[3];
    const float* wk = (const float*)d_in[4];
    const float* wv = (const float*)d_in[5];
    const float* wo = (const float*)d_in[6];
    float* out = (float*)d_out;

    float* qkv;
    cudaGetSymbolAddress((void**)&qkv, g_qkv);

    __half *xh, *atth, *wqkvT, *woT;
    cudaGetSymbolAddress((void**)&xh,    g_xh);
    cudaGetSymbolAddress((void**)&atth,  g_atth);
    cudaGetSymbolAddress((void**)&wqkvT, g_wqkvT);
    cudaGetSymbolAddress((void**)&woT,   g_woT);

    __nv_bfloat16 *qsh, *qsl, *ksh, *ksl, *vsh, *vsl;
    cudaGetSymbolAddress((void**)&qsh, g_qs_hi); cudaGetSymbolAddress((void**)&qsl, g_qs_lo);
    cudaGetSymbolAddress((void**)&ksh, g_ks_hi); cudaGetSymbolAddress((void**)&ksl, g_ks_lo);
    cudaGetSymbolAddress((void**)&vsh, g_vs_hi); cudaGetSymbolAddress((void**)&vsl, g_vs_lo);

    cudaFuncSetAttribute(gemm_h,
                         cudaFuncAttributeMaxDynamicSharedMemorySize, GEMM_SMEM);
    cudaFuncSetAttribute(attn_tc,
                         cudaFuncAttributeMaxDynamicSharedMemorySize, ATT_SMEM);

    // launches 1-4: convert x + q/k/v weights (wk/wv rows appended in wqkvT)
    hconv_kernel<<<(SEQ * DIM / 4 + 255) / 256, 256>>>(x, xh, SEQ * DIM / 4);
    tconv_kernel<<<dim3(DIM / 32, DIM / 32), dim3(32, 8)>>>(wq, wqkvT, DIM, DIM);
    tconv_kernel<<<dim3(KVD / 32, DIM / 32), dim3(32, 8)>>>(
        wk, wqkvT + (size_t)DIM * DIM, DIM, KVD);
    tconv_kernel<<<dim3(KVD / 32, DIM / 32), dim3(32, 8)>>>(
        wv, wqkvT + (size_t)(DIM + KVD) * DIM, DIM, KVD);

    // launch 5: merged QKV projection (profiled by ncu)
    gemm_h<<<dim3(QKVD / 256, SEQ / 128), 256, GEMM_SMEM>>>(
        xh, wqkvT, qkv, SEQ, QKVD, DIM);

    // remaining prep + attention + O-projection
    tconv_kernel<<<dim3(DIM / 32, DIM / 32), dim3(32, 8)>>>(wo, woT, DIM, DIM);

    int nrope = SEQ * (NH + NKV) * (HD / 2);
    rope_split_kernel<<<(nrope + 255) / 256, 256>>>(qkv, fc, fs, qsh, qsl, ksh, ksl);
    vsplit_kernel<<<(SEQ * KVD / 4 + 255) / 256, 256>>>(qkv, vsh, vsl);

    attn_tc<<<dim3(SEQ / 128, NH), 256, ATT_SMEM>>>(qsh, qsl, ksh, ksl, vsh, vsl, atth);

    gemm_h<<<dim3(DIM / 256, SEQ / 128), 256, GEMM_SMEM>>>(atth, woT, out, SEQ, DIM, DIM);
}

// round 15
// speedup vs baseline: 1.0014x; 1.0005x over previous
#include <cuda_runtime.h>
#include <cuda_bf16.h>
#include <cuda_fp16.h>
#include <math.h>
#include <stdint.h>

#define SEQ   2048
#define DIM   4096
#define NH    32
#define NKV   8
#define HD    128
#define KVD   1024
#define QKVD  6144          // DIM + 2*KVD (merged q|k|v output)
#define SCALE 0.08838834764831845f

// ---------------- scratch ----------------------------------------------------
__device__ float g_qkv[SEQ * QKVD];        // merged q|k|v projection output

__device__ __half g_xh[SEQ * DIM];
__device__ __half g_atth[SEQ * DIM];
__device__ __half g_wqkvT[QKVD * DIM];     // [wq^T ; wk^T ; wv^T] rows
__device__ __half g_woT[DIM * DIM];

// bf16 split Q/K/V for attention (Q pre-scaled, RoPE applied)
__device__ __nv_bfloat16 g_qs_hi[SEQ * DIM], g_qs_lo[SEQ * DIM];
__device__ __nv_bfloat16 g_ks_hi[SEQ * KVD], g_ks_lo[SEQ * KVD];
__device__ __nv_bfloat16 g_vs_hi[SEQ * KVD], g_vs_lo[SEQ * KVD];

// ---------------- PTX helpers (baseline PTX only) -----------------------------
__device__ __forceinline__ uint32_t smem_u32(const void* p) {
    uint32_t a;
    asm("{ .reg .u64 t; cvta.to.shared.u64 t, %1; cvt.u32.u64 %0, t; }"
        : "=r"(a) : "l"(p));
    return a;
}
#define CP_ASYNC16(dst, src) \
    asm volatile("cp.async.cg.shared.global [%0], [%1], 16;" :: "r"(dst), "l"(src) : "memory")
#define CP_COMMIT()  asm volatile("cp.async.commit_group;" ::: "memory")
#define CP_WAIT(n)   asm volatile("cp.async.wait_group %0;" :: "n"(n) : "memory")

#define LDSM_X4(r, addr)                                                      \
    asm volatile("ldmatrix.sync.aligned.m8n8.x4.shared.b16 {%0,%1,%2,%3}, [%4];" \
        : "=r"((r)[0]), "=r"((r)[1]), "=r"((r)[2]), "=r"((r)[3]) : "r"(addr))
#define LDSM_X4_T(r, addr)                                                    \
    asm volatile("ldmatrix.sync.aligned.m8n8.x4.trans.shared.b16 {%0,%1,%2,%3}, [%4];" \
        : "=r"((r)[0]), "=r"((r)[1]), "=r"((r)[2]), "=r"((r)[3]) : "r"(addr))

#define MMA_BF16(d, a, b0, b1)                                                \
    asm volatile("mma.sync.aligned.m16n8k16.row.col.f32.bf16.bf16.f32 "       \
        "{%0,%1,%2,%3}, {%4,%5,%6,%7}, {%8,%9}, {%0,%1,%2,%3};"               \
        : "+f"((d)[0]), "+f"((d)[1]), "+f"((d)[2]), "+f"((d)[3])              \
        : "r"((a)[0]), "r"((a)[1]), "r"((a)[2]), "r"((a)[3]), "r"(b0), "r"(b1))

#define MMA_F16(d, a, b0, b1)                                                 \
    asm volatile("mma.sync.aligned.m16n8k16.row.col.f32.f16.f16.f32 "         \
        "{%0,%1,%2,%3}, {%4,%5,%6,%7}, {%8,%9}, {%0,%1,%2,%3};"               \
        : "+f"((d)[0]), "+f"((d)[1]), "+f"((d)[2]), "+f"((d)[3])              \
        : "r"((a)[0]), "r"((a)[1]), "r"((a)[2]), "r"((a)[3]), "r"(b0), "r"(b1))

__device__ __forceinline__ uint32_t pack_bf16x2(float lo, float hi) {
    __nv_bfloat162 p = __float22bfloat162_rn(make_float2(lo, hi));
    return *(uint32_t*)&p;
}

// ---------------- fp32 -> fp16 convert (elementwise) ---------------------------
__global__ void hconv_kernel(const float* __restrict__ in,
                             __half* __restrict__ out, int n4)
{
    int i = blockIdx.x * blockDim.x + threadIdx.x;
    if (i >= n4) return;
    float4 v = ((const float4*)in)[i];
    __half2* op = (__half2*)out;
    op[i * 2]     = __floats2half2_rn(v.x, v.y);
    op[i * 2 + 1] = __floats2half2_rn(v.z, v.w);
}

// ---------------- transpose + convert: W[K,N] fp32 -> WT[N,K] fp16 -------------
__global__ void tconv_kernel(const float* __restrict__ B,
                             __half* __restrict__ T, int K, int N)
{
    __shared__ float tile[32][33];
    int n0 = blockIdx.x * 32, k0 = blockIdx.y * 32;
    int tx = threadIdx.x, ty = threadIdx.y;
#pragma unroll
    for (int i = 0; i < 32; i += 8)
        tile[ty + i][tx] = B[(size_t)(k0 + ty + i) * N + n0 + tx];
    __syncthreads();
#pragma unroll
    for (int i = 0; i < 32; i += 8)
        T[(size_t)(n0 + ty + i) * K + k0 + tx] = __float2half_rn(tile[tx][ty + i]);
}

// ---------------- fp16 mma.sync GEMM: C[M,N] = A[M,K] @ B[N,K]^T ---------------
// CTA tile 128x256, BK=32, 8 warps 2x4 -> warp tile 64x64 (4x8 mma tiles).
#define BK     32
#define ASTR   40                       // smem row stride (halves)
#define A_E    (128 * ASTR)             // A tile: 5120 halves
#define B_E    (256 * ASTR)             // B tile: 10240 halves
#define BUF_E  (A_E + B_E)
#define GEMM_SMEM (2 * BUF_E * 2)       // 61440 bytes

__global__ __launch_bounds__(256, 1) void gemm_h(
    const __half* __restrict__ A, const __half* __restrict__ B,
    float* __restrict__ C, int M, int N, int K)
{
    extern __shared__ __half smh[];
    const uint32_t sbase = smem_u32(smh);
    const int t = threadIdx.x, lane = t & 31, w = t >> 5;
    const int wm = w & 1, wn = w >> 1;           // 2 x 4 warp grid
    const int m0 = blockIdx.y << 7, n0 = blockIdx.x << 8;

    const __half* srcA = A + (size_t)m0 * K;
    const __half* srcB = B + (size_t)n0 * K;

    float acc[4][8][4];
#pragma unroll
    for (int a = 0; a < 4; a++)
#pragma unroll
        for (int b = 0; b < 8; b++)
#pragma unroll
            for (int c = 0; c < 4; c++) acc[a][b][c] = 0.f;

    const int lr = t >> 2, lc = (t & 3) * 8;     // load row / col chunk (halves)

    // prologue: buffer 0
    {
        uint32_t dA = sbase;
        uint32_t dB = sbase + A_E * 2;
        CP_ASYNC16(dA + (lr * ASTR + lc) * 2,        srcA + (size_t)lr * K + lc);
        CP_ASYNC16(dA + ((lr + 64) * ASTR + lc) * 2, srcA + (size_t)(lr + 64) * K + lc);
#pragma unroll
        for (int rr = 0; rr < 4; rr++)
            CP_ASYNC16(dB + ((lr + rr * 64) * ASTR + lc) * 2,
                       srcB + (size_t)(lr + rr * 64) * K + lc);
    }
    CP_COMMIT();

    const int niter = K / BK;
    for (int i = 0; i < niter; i++) {
        const int b = i & 1;
        if (i + 1 < niter) {
            const int nb = b ^ 1;
            const size_t koff = (size_t)(i + 1) * BK;
            uint32_t dA = sbase + (uint32_t)(nb * BUF_E) * 2;
            uint32_t dB = dA + A_E * 2;
            CP_ASYNC16(dA + (lr * ASTR + lc) * 2,        srcA + (size_t)lr * K + koff + lc);
            CP_ASYNC16(dA + ((lr + 64) * ASTR + lc) * 2, srcA + (size_t)(lr + 64) * K + koff + lc);
#pragma unroll
            for (int rr = 0; rr < 4; rr++)
                CP_ASYNC16(dB + ((lr + rr * 64) * ASTR + lc) * 2,
                           srcB + (size_t)(lr + rr * 64) * K + koff + lc);
            CP_COMMIT();
            CP_WAIT(1);
        } else {
            CP_WAIT(0);
        }
        __syncthreads();

        const uint32_t As = sbase + (uint32_t)(b * BUF_E) * 2;
        const uint32_t Bs = As + A_E * 2;

#pragma unroll
        for (int ks = 0; ks < 2; ks++) {
            const int koff = ks * 16 + (lane >> 4) * 8;
            const int arow = wm * 64 + (lane & 15);
            const int brow = wn * 64 + (lane & 15);

            uint32_t af[4][4], bf[4][4];
#pragma unroll
            for (int mt = 0; mt < 4; mt++)
                LDSM_X4(af[mt], As + (uint32_t)((arow + mt * 16) * ASTR + koff) * 2);
#pragma unroll
            for (int np = 0; np < 4; np++)
                LDSM_X4(bf[np], Bs + (uint32_t)((brow + np * 16) * ASTR + koff) * 2);
#pragma unroll
            for (int mt = 0; mt < 4; mt++)
#pragma unroll
                for (int nt = 0; nt < 8; nt++) {
                    const int np = nt >> 1, sel = nt & 1;
                    MMA_F16(acc[mt][nt], af[mt], bf[np][sel], bf[np][sel + 2]);
                }
        }
        __syncthreads();
    }

#pragma unroll
    for (int mt = 0; mt < 4; mt++) {
        const int r = m0 + wm * 64 + mt * 16 + (lane >> 2);
#pragma unroll
        for (int nt = 0; nt < 8; nt++) {
            const int c = n0 + wn * 64 + nt * 8 + (lane & 3) * 2;
            *(float2*)(C + (size_t)r * N + c) =
                make_float2(acc[mt][nt][0], acc[mt][nt][1]);
            *(float2*)(C + (size_t)(r + 8) * N + c) =
                make_float2(acc[mt][nt][2], acc[mt][nt][3]);
        }
    }
}

// ---------------- fused RoPE + scale + bf16 split (reads merged qkv) ----------
__global__ void rope_split_kernel(
    const float* __restrict__ qkv,
    const float* __restrict__ fc, const float* __restrict__ fs,
    __nv_bfloat16* __restrict__ qh, __nv_bfloat16* __restrict__ ql,
    __nv_bfloat16* __restrict__ kh, __nv_bfloat16* __restrict__ kl)
{
    int idx = blockIdx.x * blockDim.x + threadIdx.x;
    const int qn = SEQ * NH * (HD / 2);
    const int kn = SEQ * NKV * (HD / 2);
    float o1, o2;
    size_t off_out;
    __nv_bfloat16 *ph, *pl;
    if (idx < qn) {
        int s = idx / (NH * 64);
        int rem = idx - s * (NH * 64);
        int h = rem >> 6, i = rem & 63;
        float c = fc[s * 64 + i], sn = fs[s * 64 + i];
        size_t off_in = (size_t)s * QKVD + h * HD + 2 * i;
        float t1 = qkv[off_in], t2 = qkv[off_in + 1];
        o1 = (t1 * c - t2 * sn) * SCALE;
        o2 = (t1 * sn + t2 * c) * SCALE;
        off_out = (size_t)s * DIM + h * HD + 2 * i;
        ph = qh; pl = ql;
    } else if (idx < qn + kn) {
        int j = idx - qn;
        int s = j / (NKV * 64);
        int rem = j - s * (NKV * 64);
        int h = rem >> 6, i = rem & 63;
        float c = fc[s * 64 + i], sn = fs[s * 64 + i];
        size_t off_in = (size_t)s * QKVD + DIM + h * HD + 2 * i;
        float t1 = qkv[off_in], t2 = qkv[off_in + 1];
        o1 = t1 * c - t2 * sn;
        o2 = t1 * sn + t2 * c;
        off_out = (size_t)s * KVD + h * HD + 2 * i;
        ph = kh; pl = kl;
    } else return;
    __nv_bfloat16 h1 = __float2bfloat16(o1);
    __nv_bfloat16 h2 = __float2bfloat16(o2);
    __nv_bfloat162 hp; hp.x = h1; hp.y = h2;
    __nv_bfloat162 lp;
    lp.x = __float2bfloat16(o1 - __bfloat162float(h1));
    lp.y = __float2bfloat16(o2 - __bfloat162float(h2));
    *(__nv_bfloat162*)(ph + off_out) = hp;
    *(__nv_bfloat162*)(pl + off_out) = lp;
}

// ---------------- strided split fp32 -> bf16 hi/lo (V from merged qkv) --------
__global__ void vsplit_kernel(const float* __restrict__ qkv,
                              __nv_bfloat16* __restrict__ hi,
                              __nv_bfloat16* __restrict__ lo)
{
    int i = blockIdx.x * blockDim.x + threadIdx.x;   // over SEQ*KVD/4
    if (i >= SEQ * KVD / 4) return;
    int row = i / (KVD / 4), c4 = i - row * (KVD / 4);
    float4 v = *(const float4*)(qkv + (size_t)row * QKVD + DIM + KVD + c4 * 4);
    __nv_bfloat16 h0 = __float2bfloat16(v.x);
    __nv_bfloat16 h1 = __float2bfloat16(v.y);
    __nv_bfloat16 h2 = __float2bfloat16(v.z);
    __nv_bfloat16 h3 = __float2bfloat16(v.w);
    size_t o = (size_t)row * KVD + c4 * 4;
    __nv_bfloat162 a; a.x = h0; a.y = h1; *(__nv_bfloat162*)(hi + o) = a;
    __nv_bfloat162 b; b.x = h2; b.y = h3; *(__nv_bfloat162*)(hi + o + 2) = b;
    __nv_bfloat162 c;
    c.x = __float2bfloat16(v.x - __bfloat162float(h0));
    c.y = __float2bfloat16(v.y - __bfloat162float(h1));
    *(__nv_bfloat162*)(lo + o) = c;
    __nv_bfloat162 d;
    d.x = __float2bfloat16(v.z - __bfloat162float(h2));
    d.y = __float2bfloat16(v.w - __bfloat162float(h3));
    *(__nv_bfloat162*)(lo + o + 2) = d;
}

// ---------------- tensor-core flash attention (R5-proven; fp16 output) --------
#define AROWB 272
#define QT_B  (128 * AROWB)
#define KT_B  (64 * AROWB)
#define KVBUF (4 * KT_B)
#define ATT_SMEM (2 * QT_B + 2 * KVBUF)

__global__ __launch_bounds__(256) void attn_tc(
    const __nv_bfloat16* __restrict__ Qh, const __nv_bfloat16* __restrict__ Ql,
    const __nv_bfloat16* __restrict__ Kh, const __nv_bfloat16* __restrict__ Kl,
    const __nv_bfloat16* __restrict__ Vh, const __nv_bfloat16* __restrict__ Vl,
    __half* __restrict__ O)
{
    extern __shared__ char smc[];
    const uint32_t sb  = smem_u32(smc);
    const int t = threadIdx.x, lane = t & 31, w = t >> 5;
    const int h = blockIdx.y, q0 = blockIdx.x << 7, kvh = h >> 2;

    const uint32_t sQh = sb;
    const uint32_t sQl = sb + QT_B;
    const uint32_t sKV = sb + 2 * QT_B;

    {
        const __nv_bfloat16* qs[2] = { Qh, Ql };
        uint32_t qd[2] = { sQh, sQl };
#pragma unroll
        for (int tn = 0; tn < 2; tn++)
#pragma unroll
            for (int p = 0; p < 8; p++) {
                int chunk = t + p * 256;
                int row = chunk >> 4, c = chunk & 15;
                CP_ASYNC16(qd[tn] + row * AROWB + c * 16,
                           qs[tn] + (size_t)(q0 + row) * DIM + h * HD + c * 8);
            }
    }
    const __nv_bfloat16* kvsrc[4] = { Kh, Kl, Vh, Vl };
#pragma unroll
    for (int tn = 0; tn < 4; tn++)
#pragma unroll
        for (int p = 0; p < 4; p++) {
            int chunk = t + p * 256;
            int row = chunk >> 4, c = chunk & 15;
            CP_ASYNC16(sKV + tn * KT_B + row * AROWB + c * 16,
                       kvsrc[tn] + (size_t)row * KVD + kvh * HD + c * 8);
        }
    CP_COMMIT();

    float m0 = -INFINITY, m1 = -INFINITY, l0 = 0.f, l1 = 0.f;
    float oacc[16][4];
#pragma unroll
    for (int i = 0; i < 16; i++)
#pragma unroll
        for (int j = 0; j < 4; j++) oacc[i][j] = 0.f;

    const int NIT = SEQ / 64;
    for (int it = 0; it < NIT; it++) {
        CP_WAIT(0);
        __syncthreads();
        const uint32_t kvb = sKV + (it & 1) * KVBUF;
        if (it + 1 < NIT) {
            const uint32_t nb = sKV + ((it + 1) & 1) * KVBUF;
            const int k0n = (it + 1) * 64;
#pragma unroll
            for (int tn = 0; tn < 4; tn++)
#pragma unroll
                for (int p = 0; p < 4; p++) {
                    int chunk = t + p * 256;
                    int row = chunk >> 4, c = chunk & 15;
                    CP_ASYNC16(nb + tn * KT_B + row * AROWB + c * 16,
                               kvsrc[tn] + (size_t)(k0n + row) * KVD + kvh * HD + c * 8);
                }
            CP_COMMIT();
        }

        float sacc[8][4];
#pragma unroll
        for (int i = 0; i < 8; i++)
#pragma unroll
            for (int j = 0; j < 4; j++) sacc[i][j] = 0.f;

#pragma unroll
        for (int ks = 0; ks < 8; ks++) {
            const uint32_t aoff = (uint32_t)(16 * w + (lane & 15)) * AROWB
                                + ks * 32 + (lane >> 4) * 16;
            uint32_t ah[4], al[4];
            LDSM_X4(ah, sQh + aoff);
            LDSM_X4(al, sQl + aoff);
#pragma unroll
            for (int g = 0; g < 4; g++) {
                const uint32_t boff = (uint32_t)(g * 16 + (lane & 15)) * AROWB
                                    + ks * 32 + (lane >> 4) * 16;
                uint32_t bh[4], bl[4];
                LDSM_X4(bh, kvb + boff);
                LDSM_X4(bl, kvb + KT_B + boff);
#pragma unroll
                for (int sel = 0; sel < 2; sel++) {
                    MMA_BF16(sacc[2 * g + sel], ah, bh[sel], bh[sel + 2]);
                    MMA_BF16(sacc[2 * g + sel], ah, bl[sel], bl[sel + 2]);
                    MMA_BF16(sacc[2 * g + sel], al, bh[sel], bh[sel + 2]);
                }
            }
        }

        float mc0 = -INFINITY, mc1 = -INFINITY;
#pragma unroll
        for (int i = 0; i < 8; i++) {
            mc0 = fmaxf(mc0, fmaxf(sacc[i][0], sacc[i][1]));
            mc1 = fmaxf(mc1, fmaxf(sacc[i][2], sacc[i][3]));
        }
        mc0 = fmaxf(mc0, __shfl_xor_sync(0xffffffffu, mc0, 1));
        mc0 = fmaxf(mc0, __shfl_xor_sync(0xffffffffu, mc0, 2));
        mc1 = fmaxf(mc1, __shfl_xor_sync(0xffffffffu, mc1, 1));
        mc1 = fmaxf(mc1, __shfl_xor_sync(0xffffffffu, mc1, 2));
        const float mn0 = fmaxf(m0, mc0), mn1 = fmaxf(m1, mc1);
        const float alpha0 = __expf(m0 - mn0), alpha1 = __expf(m1 - mn1);
        m0 = mn0; m1 = mn1;
        float sum0 = 0.f, sum1 = 0.f;
#pragma unroll
        for (int i = 0; i < 8; i++) {
            sacc[i][0] = __expf(sacc[i][0] - mn0);
            sacc[i][1] = __expf(sacc[i][1] - mn0);
            sacc[i][2] = __expf(sacc[i][2] - mn1);
            sacc[i][3] = __expf(sacc[i][3] - mn1);
            sum0 += sacc[i][0] + sacc[i][1];
            sum1 += sacc[i][2] + sacc[i][3];
        }
        sum0 += __shfl_xor_sync(0xffffffffu, sum0, 1);
        sum0 += __shfl_xor_sync(0xffffffffu, sum0, 2);
        sum1 += __shfl_xor_sync(0xffffffffu, sum1, 1);
        sum1 += __shfl_xor_sync(0xffffffffu, sum1, 2);
        l0 = l0 * alpha0 + sum0;
        l1 = l1 * alpha1 + sum1;

#pragma unroll
        for (int i = 0; i < 16; i++) {
            oacc[i][0] *= alpha0; oacc[i][1] *= alpha0;
            oacc[i][2] *= alpha1; oacc[i][3] *= alpha1;
        }

        uint32_t pah[4][4], pal[4][4];
#pragma unroll
        for (int ks = 0; ks < 4; ks++) {
#pragma unroll
            for (int half = 0; half < 2; half++) {
                const int nt = 2 * ks + half;
                float e0 = sacc[nt][0], e1 = sacc[nt][1];
                float e2 = sacc[nt][2], e3 = sacc[nt][3];
                __nv_bfloat16 h0 = __float2bfloat16(e0);
                __nv_bfloat16 h1 = __float2bfloat16(e1);
                __nv_bfloat16 h2 = __float2bfloat16(e2);
                __nv_bfloat16 h3 = __float2bfloat16(e3);
                pah[ks][2 * half + 0] = pack_bf16x2(e0, e1);
                pah[ks][2 * half + 1] = pack_bf16x2(e2, e3);
                pal[ks][2 * half + 0] = pack_bf16x2(e0 - __bfloat162float(h0),
                                                    e1 - __bfloat162float(h1));
                pal[ks][2 * half + 1] = pack_bf16x2(e2 - __bfloat162float(h2),
                                                    e3 - __bfloat162float(h3));
            }
        }

#pragma unroll
        for (int ks = 0; ks < 4; ks++) {
#pragma unroll
            for (int g = 0; g < 8; g++) {
                const uint32_t voff = (uint32_t)(ks * 16 + (lane & 15)) * AROWB
                                    + (g * 16 + (lane >> 4) * 8) * 2;
                uint32_t vh[4], vl[4];
                LDSM_X4_T(vh, kvb + 2 * KT_B + voff);
                LDSM_X4_T(vl, kvb + 3 * KT_B + voff);
#pragma unroll
                for (int sel = 0; sel < 2; sel++) {
                    MMA_BF16(oacc[2 * g + sel], pah[ks], vh[2 * sel], vh[2 * sel + 1]);
                    MMA_BF16(oacc[2 * g + sel], pah[ks], vl[2 * sel], vl[2 * sel + 1]);
                    MMA_BF16(oacc[2 * g + sel], pal[ks], vh[2 * sel], vh[2 * sel + 1]);
                }
            }
        }
    }

    const float inv0 = 1.0f / l0, inv1 = 1.0f / l1;
    const int r0 = q0 + 16 * w + (lane >> 2);
    const int r1 = r0 + 8;
#pragma unroll
    for (int nt = 0; nt < 16; nt++) {
        const int col = h * HD + nt * 8 + (lane & 3) * 2;
        *(__half2*)(O + (size_t)r0 * DIM + col) =
            __floats2half2_rn(oacc[nt][0] * inv0, oacc[nt][1] * inv0);
        *(__half2*)(O + (size_t)r1 * DIM + col) =
            __floats2half2_rn(oacc[nt][2] * inv1, oacc[nt][3] * inv1);
    }
}

// ---------------- launch -------------------------------------------------------
extern "C" void kernel_launch(void* const* d_in, const int* in_sizes, int n_in,
                              void* d_out, int out_size)
{
    const float* x  = (const float*)d_in[0];
    const float* fc = (const float*)d_in[1];
    const float* fs = (const float*)d_in[2];
    const float* wq = (const float*)d_in[3];
    const float* wk = (const float*)d_in[4];
    const float* wv = (const float*)d_in[5];
    const float* wo = (const float*)d_in[6];
    float* out = (float*)d_out;

    float* qkv;
    cudaGetSymbolAddress((void**)&qkv, g_qkv);

    __half *xh, *atth, *wqkvT, *woT;
    cudaGetSymbolAddress((void**)&xh,    g_xh);
    cudaGetSymbolAddress((void**)&atth,  g_atth);
    cudaGetSymbolAddress((void**)&wqkvT, g_wqkvT);
    cudaGetSymbolAddress((void**)&woT,   g_woT);

    __nv_bfloat16 *qsh, *qsl, *ksh, *ksl, *vsh, *vsl;
    cudaGetSymbolAddress((void**)&qsh, g_qs_hi); cudaGetSymbolAddress((void**)&qsl, g_qs_lo);
    cudaGetSymbolAddress((void**)&ksh, g_ks_hi); cudaGetSymbolAddress((void**)&ksl, g_ks_lo);
    cudaGetSymbolAddress((void**)&vsh, g_vs_hi); cudaGetSymbolAddress((void**)&vsl, g_vs_lo);

    cudaFuncSetAttribute(gemm_h,
                         cudaFuncAttributeMaxDynamicSharedMemorySize, GEMM_SMEM);
    cudaFuncSetAttribute(attn_tc,
                         cudaFuncAttributeMaxDynamicSharedMemorySize, ATT_SMEM);

    // launches 1-4: convert x + q/k/v weights (wk/wv rows appended in wqkvT)
    hconv_kernel<<<(SEQ * DIM / 4 + 255) / 256, 256>>>(x, xh, SEQ * DIM / 4);
    tconv_kernel<<<dim3(DIM / 32, DIM / 32), dim3(32, 8)>>>(wq, wqkvT, DIM, DIM);
    tconv_kernel<<<dim3(KVD / 32, DIM / 32), dim3(32, 8)>>>(
        wk, wqkvT + (size_t)DIM * DIM, DIM, KVD);
    tconv_kernel<<<dim3(KVD / 32, DIM / 32), dim3(32, 8)>>>(
        wv, wqkvT + (size_t)(DIM + KVD) * DIM, DIM, KVD);

    // launch 5: merged QKV projection (profiled by ncu)
    gemm_h<<<dim3(QKVD / 256, SEQ / 128), 256, GEMM_SMEM>>>(
        xh, wqkvT, qkv, SEQ, QKVD, DIM);

    // remaining prep + attention + O-projection
    tconv_kernel<<<dim3(DIM / 32, DIM / 32), dim3(32, 8)>>>(wo, woT, DIM, DIM);

    int nrope = SEQ * (NH + NKV) * (HD / 2);
    rope_split_kernel<<<(nrope + 255) / 256, 256>>>(qkv, fc, fs, qsh, qsl, ksh, ksl);
    vsplit_kernel<<<(SEQ * KVD / 4 + 255) / 256, 256>>>(qkv, vsh, vsl);

    attn_tc<<<dim3(SEQ / 128, NH), 256, ATT_SMEM>>>(qsh, qsl, ksh, ksl, vsh, vsl, atth);

    gemm_h<<<dim3(DIM / 256, SEQ / 128), 256, GEMM_SMEM>>>(atth, woT, out, SEQ, DIM, DIM);
}